// round 12
// baseline (speedup 1.0000x reference)
#include <cuda_runtime.h>
#include <cuda_bf16.h>
#include <cstdint>

// ---------------- model dims ----------------
#define TOK   2048            // B*N = 4*512
#define NSEQ  512
#define BATCH 4
#define DDIM  256
#define HEADS 8
#define DH    32
#define MFEAT 110
#define NLAYERS 8
#define HID   256
#define FFDIM 1024

#define CHUNK  32
#define NCHUNK 16
#define STATE  (MFEAT*33)     // 110 x (32 S-cols + 1 z) = 3630

#define SCALE_Q 0.42044820762685725f   // 32^-0.25
#define MNS     0.09534625892455924f   // 110^-0.5
#define EPS_K   1e-4f
#define EPS_D   1e-6f

// ---------------- scratch (device globals; no runtime alloc) -----------------
__device__ float    g_h  [TOK*DDIM];
__device__ float    g_y  [TOK*DDIM];
__device__ float    g_q  [TOK*DDIM];
__device__ float    g_k  [TOK*DDIM];
__device__ float    g_v  [TOK*DDIM];
__device__ float    g_o  [TOK*DDIM];
__device__ float    g_ff [TOK*FFDIM];
__device__ float    g_qp [32*NSEQ*MFEAT];
__device__ float    g_kp [32*NSEQ*MFEAT];
__device__ unsigned g_stab[32];
__device__ float    g_T  [32*NCHUNK*STATE];     // chunk totals
__device__ float    g_gi [2*TOK*1024];
__device__ float    g_l0 [TOK*512];
__device__ float    g_l1 [TOK*512];

// ---------------- helpers ----------------
__device__ __forceinline__ float wsum(float v) {
    #pragma unroll
    for (int o = 16; o > 0; o >>= 1) v += __shfl_xor_sync(0xffffffffu, v, o);
    return v;
}
__device__ __forceinline__ float wmaxf(float v) {
    #pragma unroll
    for (int o = 16; o > 0; o >>= 1) v = fmaxf(v, __shfl_xor_sync(0xffffffffu, v, o));
    return v;
}
__device__ __forceinline__ unsigned fenc(float f) {
    unsigned u = __float_as_uint(f);
    return (u & 0x80000000u) ? ~u : (u | 0x80000000u);
}
__device__ __forceinline__ float fdec(unsigned e) {
    unsigned u = (e & 0x80000000u) ? (e ^ 0x80000000u) : ~e;
    return __uint_as_float(u);
}
__device__ __forceinline__ float sigm(float x) { return 1.0f / (1.0f + expf(-x)); }

// packed fp32x2 FMA (Blackwell)
__device__ __forceinline__ void ffma2(unsigned long long& c, unsigned long long a, unsigned long long b) {
    asm("fma.rn.f32x2 %0, %1, %2, %3;" : "=l"(c) : "l"(a), "l"(b), "l"(c));
}
__device__ __forceinline__ float f2lo(unsigned long long v) { return __uint_as_float((unsigned)v); }
__device__ __forceinline__ float f2hi(unsigned long long v) { return __uint_as_float((unsigned)(v >> 32)); }

// tf32 helpers
__device__ __forceinline__ unsigned f2tf(float x) {
    unsigned r;
    asm("cvt.rna.tf32.f32 %0, %1;" : "=r"(r) : "f"(x));
    return r;
}
__device__ __forceinline__ void mma_tf32(float c[4], unsigned a0, unsigned a1, unsigned a2, unsigned a3,
                                         unsigned b0, unsigned b1) {
    asm("mma.sync.aligned.m16n8k8.row.col.f32.tf32.tf32.f32 "
        "{%0,%1,%2,%3}, {%4,%5,%6,%7}, {%8,%9}, {%0,%1,%2,%3};"
        : "+f"(c[0]), "+f"(c[1]), "+f"(c[2]), "+f"(c[3])
        : "r"(a0), "r"(a1), "r"(a2), "r"(a3), "r"(b0), "r"(b1));
}

// ---------------- TF32 tensor-core GEMM: C[M,N] = A[M,K] @ W[N,K]^T ----------
// tile 64x64, 128 threads (4 warps), warp tile 32x32 (2 m16 x 4 n8), k-stage 16
__device__ __forceinline__ void gemm_tile(const float* __restrict__ A, const float* __restrict__ W,
                                          const float* __restrict__ bias1, const float* __restrict__ bias2,
                                          const float* __restrict__ res, float* __restrict__ C,
                                          int M, int N, int K, int act, int m0, int n0)
{
    __shared__ unsigned As[16][72];
    __shared__ unsigned Ws[16][72];
    int t = threadIdx.x;                 // 128
    int warp = t >> 5, lane = t & 31;
    int mw = (warp & 1) * 32, nw = (warp >> 1) * 32;
    int g = lane >> 2, tg = lane & 3;

    float acc[2][4][4];
    #pragma unroll
    for (int mi = 0; mi < 2; mi++)
        #pragma unroll
        for (int j = 0; j < 4; j++)
            #pragma unroll
            for (int e = 0; e < 4; e++) acc[mi][j][e] = 0.f;

    int lrow = t >> 1, lk8 = (t & 1) * 8;
    const float* Ap = A + (size_t)(m0 + lrow) * K + lk8;
    const float* Wp = W + (size_t)(n0 + lrow) * K + lk8;

    for (int k0 = 0; k0 < K; k0 += 16) {
        float4 av0 = *(const float4*)(Ap + k0);
        float4 av1 = *(const float4*)(Ap + k0 + 4);
        float4 wv0 = *(const float4*)(Wp + k0);
        float4 wv1 = *(const float4*)(Wp + k0 + 4);
        As[lk8+0][lrow] = f2tf(av0.x); As[lk8+1][lrow] = f2tf(av0.y);
        As[lk8+2][lrow] = f2tf(av0.z); As[lk8+3][lrow] = f2tf(av0.w);
        As[lk8+4][lrow] = f2tf(av1.x); As[lk8+5][lrow] = f2tf(av1.y);
        As[lk8+6][lrow] = f2tf(av1.z); As[lk8+7][lrow] = f2tf(av1.w);
        Ws[lk8+0][lrow] = f2tf(wv0.x); Ws[lk8+1][lrow] = f2tf(wv0.y);
        Ws[lk8+2][lrow] = f2tf(wv0.z); Ws[lk8+3][lrow] = f2tf(wv0.w);
        Ws[lk8+4][lrow] = f2tf(wv1.x); Ws[lk8+5][lrow] = f2tf(wv1.y);
        Ws[lk8+6][lrow] = f2tf(wv1.z); Ws[lk8+7][lrow] = f2tf(wv1.w);
        __syncthreads();
        #pragma unroll
        for (int kk = 0; kk < 16; kk += 8) {
            unsigned a[2][4], b[4][2];
            #pragma unroll
            for (int mi = 0; mi < 2; mi++) {
                int mb = mw + 16*mi + g;
                a[mi][0] = As[kk+tg  ][mb];
                a[mi][1] = As[kk+tg  ][mb+8];
                a[mi][2] = As[kk+tg+4][mb];
                a[mi][3] = As[kk+tg+4][mb+8];
            }
            #pragma unroll
            for (int j = 0; j < 4; j++) {
                int nb = nw + 8*j + g;
                b[j][0] = Ws[kk+tg  ][nb];
                b[j][1] = Ws[kk+tg+4][nb];
            }
            #pragma unroll
            for (int mi = 0; mi < 2; mi++)
                #pragma unroll
                for (int j = 0; j < 4; j++)
                    mma_tf32(acc[mi][j], a[mi][0], a[mi][1], a[mi][2], a[mi][3], b[j][0], b[j][1]);
        }
        __syncthreads();
    }

    #pragma unroll
    for (int mi = 0; mi < 2; mi++) {
        #pragma unroll
        for (int j = 0; j < 4; j++) {
            int col = n0 + nw + 8*j + 2*tg;
            float b1x = 0.f, b1y = 0.f, b2x = 0.f, b2y = 0.f;
            if (bias1) { float2 bv = *(const float2*)(bias1 + col); b1x = bv.x; b1y = bv.y; }
            if (bias2) { float2 bv = *(const float2*)(bias2 + col); b2x = bv.x; b2y = bv.y; }
            #pragma unroll
            for (int half = 0; half < 2; half++) {
                int row = m0 + mw + 16*mi + g + 8*half;
                float v0 = acc[mi][j][2*half+0] + b1x + b2x;
                float v1 = acc[mi][j][2*half+1] + b1y + b2y;
                if (act == 1) {
                    v0 = 0.5f*v0*(1.0f + erff(v0*0.7071067811865476f));
                    v1 = 0.5f*v1*(1.0f + erff(v1*0.7071067811865476f));
                }
                if (res) {
                    float2 rv = *(const float2*)(res + (size_t)row*N + col);
                    v0 += rv.x; v1 += rv.y;
                }
                *(float2*)(C + (size_t)row*N + col) = make_float2(v0, v1);
            }
        }
    }
}

__global__ void __launch_bounds__(128) gemm_kernel(const float* __restrict__ A, const float* __restrict__ W,
                            const float* __restrict__ bias1, const float* __restrict__ bias2,
                            const float* __restrict__ res, float* __restrict__ C,
                            int M, int N, int K, int act)
{
    gemm_tile(A, W, bias1, bias2, res, C, M, N, K, act, blockIdx.y*64, blockIdx.x*64);
}

__global__ void __launch_bounds__(128) qkv_kernel(const float* __restrict__ A,
                           const float* __restrict__ Wq_, const float* __restrict__ Wk_, const float* __restrict__ Wv_,
                           const float* __restrict__ bq_, const float* __restrict__ bk_, const float* __restrict__ bv_,
                           float* __restrict__ Cq, float* __restrict__ Ck, float* __restrict__ Cv)
{
    int z = blockIdx.z;
    const float* W = (z == 0) ? Wq_ : (z == 1) ? Wk_ : Wv_;
    const float* b = (z == 0) ? bq_ : (z == 1) ? bk_ : bv_;
    float*       C = (z == 0) ? Cq  : (z == 1) ? Ck  : Cv;
    gemm_tile(A, W, b, nullptr, nullptr, C, TOK, 256, 256, 0, blockIdx.y*64, blockIdx.x*64);
}

// ---------------- layernorm: one warp per row, 8 rows per block --------------
__global__ void __launch_bounds__(256) ln_kernel(const float* __restrict__ x, const float* __restrict__ w,
                          const float* __restrict__ b, float* __restrict__ y,
                          unsigned* __restrict__ stab)
{
    int t = threadIdx.x;
    if (stab && blockIdx.x == 0 && t < 32) stab[t] = 0x007FFFFFu;
    int warp = t >> 5, lane = t & 31;
    int row = blockIdx.x*8 + warp;
    const float* xr = x + (size_t)row*256;
    float v[8];
    float s1 = 0.f, s2 = 0.f;
    #pragma unroll
    for (int j = 0; j < 8; j++) {
        v[j] = xr[lane + 32*j];
        s1 += v[j];
        s2 += v[j]*v[j];
    }
    s1 = wsum(s1);
    s2 = wsum(s2);
    float mu = s1 * (1.0f/256.0f);
    float ri = rsqrtf(s2*(1.0f/256.0f) - mu*mu + 1e-5f);
    float* yr = y + (size_t)row*256;
    #pragma unroll
    for (int j = 0; j < 8; j++) {
        int col = lane + 32*j;
        yr[col] = (v[j] - mu)*ri*w[col] + b[col];
    }
}

// ---------------- FAVOR+ features, merged q/k via blockIdx.z, 4 rows/warp ----
__global__ void __launch_bounds__(128) feat_kernel(const float* __restrict__ qin, const float* __restrict__ kin,
                            const float* __restrict__ proj,
                            float* __restrict__ qp, float* __restrict__ kp,
                            unsigned* __restrict__ stab)
{
    int mode = blockIdx.z;                // 0 = query, 1 = key
    const float* qk = mode ? kin : qin;
    float* out = mode ? kp : qp;
    __shared__ float proj_s[110*33];
    int t = threadIdx.x;   // 128
    for (int i = t; i < 110*33; i += 128) {
        int m = i / 33, d = i - m*33;
        proj_s[i] = (d < 32) ? proj[m*32 + d] : 0.f;
    }
    __syncthreads();
    int warp = t >> 5, lane = t & 31;
    int row0 = blockIdx.x * 32;           // 32 rows per block
    for (int rr = warp*4; rr < 32; rr += 16) {
        float xd[4], dd[4][4];
        #pragma unroll
        for (int q = 0; q < 4; q++) {
            int row = row0 + rr + q;
            int bh = row >> 9, n = row & 511;
            xd[q] = qk[(size_t)((bh >> 3)*512 + n)*256 + (bh & 7)*32 + lane] * SCALE_Q;
            #pragma unroll
            for (int mb = 0; mb < 4; mb++) dd[q][mb] = 0.f;
        }
        #pragma unroll
        for (int d = 0; d < 32; d++) {
            float xv[4];
            #pragma unroll
            for (int q = 0; q < 4; q++) xv[q] = __shfl_sync(0xffffffffu, xd[q], d);
            float p0 = proj_s[lane*33 + d];
            float p1 = proj_s[(lane+32)*33 + d];
            float p2 = proj_s[(lane+64)*33 + d];
            #pragma unroll
            for (int q = 0; q < 4; q++) {
                dd[q][0] += xv[q]*p0;
                dd[q][1] += xv[q]*p1;
                dd[q][2] += xv[q]*p2;
            }
            if (lane < 14) {
                float p3 = proj_s[(lane+96)*33 + d];
                #pragma unroll
                for (int q = 0; q < 4; q++) dd[q][3] += xv[q]*p3;
            }
        }
        #pragma unroll
        for (int q = 0; q < 4; q++) {
            int row = row0 + rr + q;
            int bh = row >> 9;
            float diag = 0.5f * wsum(xd[q]*xd[q]);
            float mx = fmaxf(fmaxf(dd[q][0], dd[q][1]), dd[q][2]);
            if (lane < 14) mx = fmaxf(mx, dd[q][3]);
            mx = wmaxf(mx);
            float* orow = out + (size_t)row*MFEAT;
            if (mode) {
                orow[lane]      = dd[q][0] - diag;
                orow[lane+32]   = dd[q][1] - diag;
                orow[lane+64]   = dd[q][2] - diag;
                if (lane < 14) orow[lane+96] = dd[q][3] - diag;
                if (lane == 0) atomicMax(&stab[bh], fenc(mx));
            } else {
                orow[lane]      = MNS*(expf(dd[q][0] - diag - mx) + EPS_K);
                orow[lane+32]   = MNS*(expf(dd[q][1] - diag - mx) + EPS_K);
                orow[lane+64]   = MNS*(expf(dd[q][2] - diag - mx) + EPS_K);
                if (lane < 14) orow[lane+96] = MNS*(expf(dd[q][3] - diag - mx) + EPS_K);
            }
        }
    }
}

// ---------------- attention pass 1: normalize kp + per-chunk totals ----------
__global__ void attn_sum_kernel(float* __restrict__ kp, const float* __restrict__ v,
                                const unsigned* __restrict__ stab, float* __restrict__ T)
{
    __shared__ float kp_c[CHUNK*MFEAT];
    __shared__ float v_c [CHUNK*32];
    int ch = blockIdx.x, bh = blockIdx.y;
    int b = bh >> 3, h = bh & 7;
    int t = threadIdx.x;                 // 256
    float stv = fdec(stab[bh]);
    float* kpb = kp + (size_t)bh*NSEQ*MFEAT + (size_t)ch*CHUNK*MFEAT;
    for (int i = t; i < CHUNK*MFEAT; i += 256) {
        float e = MNS*(expf(kpb[i] - stv) + EPS_K);
        kp_c[i] = e;
        kpb[i] = e;                      // normalized for attn_scan
    }
    for (int i = t; i < CHUNK*32; i += 256) {
        int n = i >> 5, d = i & 31;
        v_c[i] = v[(size_t)(b*512 + ch*CHUNK + n)*256 + h*32 + d];
    }
    __syncthreads();

    int mg = t >> 5, d = t & 31;
    float S[14];
    #pragma unroll
    for (int j = 0; j < 14; j++) S[j] = 0.f;
    for (int n = 0; n < CHUNK; n++) {
        float vd = v_c[n*32 + d];
        #pragma unroll
        for (int j = 0; j < 14; j++) {
            int m = mg + 8*j;
            if (m < MFEAT) S[j] += kp_c[n*MFEAT + m]*vd;
        }
    }
    float* Tb = T + (size_t)(bh*NCHUNK + ch)*STATE;
    #pragma unroll
    for (int j = 0; j < 14; j++) {
        int m = mg + 8*j;
        if (m < MFEAT) Tb[m*33 + d] = S[j];
    }
    if (t < MFEAT) {
        float z = 0.f;
        for (int n = 0; n < CHUNK; n++) z += kp_c[n*MFEAT + t];
        Tb[t*33 + 32] = z;
    }
}

// ---------------- attention pass 2: within-chunk scan, double-buffered -------
__global__ void attn_scan_kernel(const float* __restrict__ qp, const float* __restrict__ kp,
                                 const float* __restrict__ v, const float* __restrict__ T,
                                 float* __restrict__ o)
{
    __shared__ float kp_c[CHUNK*MFEAT];
    __shared__ float qp_c[CHUNK*MFEAT];
    __shared__ float v_c [CHUNK*32];
    __shared__ float qz_s[2][MFEAT];
    __shared__ float part_s[2][8][33];
    int ch = blockIdx.x, bh = blockIdx.y;
    int b = bh >> 3, h = bh & 7;
    int t = threadIdx.x;                 // 256
    const float* kpb = kp + (size_t)bh*NSEQ*MFEAT + (size_t)ch*CHUNK*MFEAT;
    const float* qpb = qp + (size_t)bh*NSEQ*MFEAT + (size_t)ch*CHUNK*MFEAT;
    for (int i = t; i < CHUNK*MFEAT; i += 256) { kp_c[i] = kpb[i]; qp_c[i] = qpb[i]; }
    for (int i = t; i < CHUNK*32; i += 256) {
        int n = i >> 5, d = i & 31;
        v_c[i] = v[(size_t)(b*512 + ch*CHUNK + n)*256 + h*32 + d];
    }
    int mg = t >> 5, d = t & 31;
    // inline exclusive prefix over earlier chunks (same summation order)
    float S[14];
    #pragma unroll
    for (int j = 0; j < 14; j++) S[j] = 0.f;
    float z = 0.f;
    for (int c = 0; c < ch; c++) {
        const float* Tc = T + (size_t)(bh*NCHUNK + c)*STATE;
        #pragma unroll
        for (int j = 0; j < 14; j++) {
            int m = mg + 8*j;
            if (m < MFEAT) S[j] += Tc[m*33 + d];
        }
        if (t < MFEAT) z += Tc[t*33 + 32];
    }
    __syncthreads();

    for (int n = 0; n < CHUNK; n++) {
        int pb = n & 1;
        if (t < MFEAT) { z += kp_c[n*MFEAT + t]; qz_s[pb][t] = qp_c[n*MFEAT + t]*z; }
        float vd = v_c[n*32 + d];
        float acc = 0.f;
        #pragma unroll
        for (int j = 0; j < 14; j++) {
            int m = mg + 8*j;
            if (m < MFEAT) {
                S[j] += kp_c[n*MFEAT + m]*vd;
                acc  += qp_c[n*MFEAT + m]*S[j];
            }
        }
        part_s[pb][mg][d] = acc;
        __syncthreads();
        if (t < 32) {
            float qs = qz_s[pb][t] + qz_s[pb][t+32] + qz_s[pb][t+64] + ((t < 14) ? qz_s[pb][t+96] : 0.f);
            float denom = wsum(qs) + EPS_D;
            float s = 0.f;
            #pragma unroll
            for (int g = 0; g < 8; g++) s += part_s[pb][g][t];
            o[(size_t)(b*512 + ch*CHUNK + n)*256 + h*32 + t] = s / denom;
        }
        // no trailing sync: next iter writes the other buffer
    }
}

// ---------------- BiLSTM scan: 8-CTA cluster, st.async mbarrier handshake ----
// even/odd lane pairs split K; gate nonlinearities parallel on even lanes
__global__ void __cluster_dims__(8,1,1) __launch_bounds__(256,1)
lstm_kernel(const float* __restrict__ gi,      // [2][2048][1024] dir-major
            const float* __restrict__ whh,     // [2][1024][256]  dir-major
            float* __restrict__ out)           // [2048][512]
{
    __shared__ __align__(16) float h_buf[512];
    __shared__ float gates_s[128];
    __shared__ __align__(16) unsigned long long mbar[2];

    int t   = threadIdx.x;              // 256
    int cta = blockIdx.x;
    int r   = cta & 7;
    int s   = cta >> 3;
    int b   = s >> 1, dir = s & 1;

    const float* whh_d = whh + (size_t)dir*1024*256;
    const float* gi_d  = gi  + (size_t)dir*TOK*1024 + (size_t)b*512*1024;

    int row  = t >> 1;                  // 0..127 (gate*32 + unit)
    int half = t & 1;
    int gate = row >> 5, jl = row & 31;
    const float* wp = whh_d + (size_t)(gate*256 + 32*r + jl)*256 + 128*half;

    unsigned long long w2[64];
    #pragma unroll
    for (int c = 0; c < 32; c++) {
        ulonglong2 u = *(const ulonglong2*)(wp + 4*c);
        w2[2*c]   = u.x;
        w2[2*c+1] = u.y;
    }

    h_buf[t] = 0.f;
    h_buf[256 + t] = 0.f;
    uint32_t hb = (uint32_t)__cvta_generic_to_shared(h_buf);
    uint32_t mb = (uint32_t)__cvta_generic_to_shared(mbar);
    if (t == 0) {
        asm volatile("mbarrier.init.shared.b64 [%0], 1;" :: "r"(mb)     : "memory");
        asm volatile("mbarrier.init.shared.b64 [%0], 1;" :: "r"(mb + 8) : "memory");
    }
    float c_reg = 0.f;
    int gidx = gate*256 + 32*r + jl;
    __syncthreads();
    asm volatile("barrier.cluster.arrive.aligned;\n\tbarrier.cluster.wait.aligned;" ::: "memory");

    uint32_t peer_base[8];
    if (t < 32) {
        #pragma unroll
        for (int p = 0; p < 8; p++) {
            uint32_t pb;
            asm volatile("mapa.shared::cluster.u32 %0, %1, %2;" : "=r"(pb) : "r"(hb), "r"(p));
            peer_base[p] = pb;
        }
    }
    uint32_t mb_off = mb - hb;

    float pg = 0.f;
    if (half == 0) pg = gi_d[(size_t)(dir ? 511 : 0)*1024 + gidx];

    int par0 = 0, par1 = 0;
    for (int step = 0; step < 512; step++) {
        int mi = step & 1;
        if (step > 0) {
            uint32_t ma = mb + mi*8;
            int ph = mi ? par1 : par0;
            unsigned done;
            asm volatile(
                "{\n\t.reg .pred p;\n\t"
                "mbarrier.try_wait.parity.acquire.cta.shared::cta.b64 p, [%1], %2;\n\t"
                "selp.b32 %0, 1, 0, p;\n\t}"
                : "=r"(done) : "r"(ma), "r"(ph) : "memory");
            if (!done) {
                asm volatile(
                    "{\n\t.reg .pred P1;\n\t"
                    "WL_%=:\n\t"
                    "mbarrier.try_wait.parity.acquire.cta.shared::cta.b64 P1, [%0], %1, 0x989680;\n\t"
                    "@P1 bra.uni WD_%=;\n\t"
                    "bra.uni WL_%=;\n\t"
                    "WD_%=:\n\t}"
                    :: "r"(ma), "r"(ph) : "memory");
            }
            if (mi) par1 ^= 1; else par0 ^= 1;
        }
        if (t == 0 && step + 1 < 512) {
            uint32_t ma = mb + (mi ^ 1)*8;
            asm volatile("mbarrier.arrive.expect_tx.shared.b64 _, [%0], %1;"
                         :: "r"(ma), "r"(1024) : "memory");
        }
        int n = dir ? (511 - step) : step;
        const float* hr = h_buf + mi*256 + 128*half;
        unsigned long long a0 = 0ull, a1 = 0ull, a2 = 0ull, a3 = 0ull;
        #pragma unroll
        for (int c = 0; c < 16; c++) {
            ulonglong2 h0 = *(const ulonglong2*)(hr + 8*c);
            ulonglong2 h1 = *(const ulonglong2*)(hr + 8*c + 4);
            ffma2(a0, w2[4*c+0], h0.x);
            ffma2(a1, w2[4*c+1], h0.y);
            ffma2(a2, w2[4*c+2], h1.x);
            ffma2(a3, w2[4*c+3], h1.y);
        }
        float acc = (f2lo(a0) + f2hi(a0)) + (f2lo(a1) + f2hi(a1))
                  + (f2lo(a2) + f2hi(a2)) + (f2lo(a3) + f2hi(a3));
        acc += __shfl_xor_sync(0xffffffffu, acc, 1);   // combine halves
        if (half == 0) {
            float val = pg + acc;
            gates_s[row] = (gate == 2) ? tanhf(val) : sigm(val);
            if (step + 1 < 512)
                pg = gi_d[(size_t)(dir ? (510 - step) : (step + 1))*1024 + gidx];
        }
        __syncthreads();
        if (t < 32) {
            float Si = gates_s[t], Sf = gates_s[32+t], Tg = gates_s[64+t], So = gates_s[96+t];
            c_reg = Sf*c_reg + Si*Tg;
            float hval = So*tanhf(c_reg);
            out[(size_t)(b*512 + n)*512 + dir*256 + 32*r + t] = hval;
            if (step + 1 < 512) {
                uint32_t off_h = (uint32_t)((((mi ^ 1)*256) + 32*r + t) << 2);
                uint32_t rm_off = mb_off + (uint32_t)((mi ^ 1)*8);
                unsigned hv = __float_as_uint(hval);
                #pragma unroll
                for (int p = 0; p < 8; p++) {
                    uint32_t ra = peer_base[p] + off_h;
                    uint32_t rm = peer_base[p] + rm_off;
                    asm volatile("st.async.shared::cluster.mbarrier::complete_tx::bytes.b32 [%0], %1, [%2];"
                                 :: "r"(ra), "r"(hv), "r"(rm) : "memory");
                }
            }
        }
        // gates_s reuse is safe: local mbarrier can't complete until local
        // writers (t<32) have read gates_s and issued their st.async.
    }
}

// ---------------- final head ----------------
__global__ void fc_kernel(const float* __restrict__ hin, const float* __restrict__ fw,
                          const float* __restrict__ fb, float* __restrict__ outp)
{
    int t = threadIdx.x;           // 128
    int warp = t >> 5, lane = t & 31;
    const float* rowp = hin + (size_t)(warp*512 + 511)*512;
    float s = 0.f;
    for (int j = lane; j < 512; j += 32) s += rowp[j]*fw[j];
    s = wsum(s);
    if (lane == 0) outp[warp] = s + fb[0];
}

// ---------------- launch ----------------
static float* sym_f(const void* s) { void* p = nullptr; cudaGetSymbolAddress(&p, s); return (float*)p; }

extern "C" void kernel_launch(void* const* d_in, const int* in_sizes, int n_in,
                              void* d_out, int out_size)
{
    (void)in_sizes; (void)n_in; (void)out_size;
    const float* x      = (const float*)d_in[0];
    const float* Win_w  = (const float*)d_in[1];
    const float* Win_b  = (const float*)d_in[2];
    const float* ln1_w  = (const float*)d_in[3];
    const float* ln1_b  = (const float*)d_in[4];
    const float* Wq     = (const float*)d_in[5];
    const float* bq     = (const float*)d_in[6];
    const float* Wk     = (const float*)d_in[7];
    const float* bk     = (const float*)d_in[8];
    const float* Wv     = (const float*)d_in[9];
    const float* bv     = (const float*)d_in[10];
    const float* Wo     = (const float*)d_in[11];
    const float* bo     = (const float*)d_in[12];
    const float* proj   = (const float*)d_in[13];
    const float* ln2_w  = (const float*)d_in[14];
    const float* ln2_b  = (const float*)d_in[15];
    const float* Wff1   = (const float*)d_in[16];
    const float* bff1   = (const float*)d_in[17];
    const float* Wff2   = (const float*)d_in[18];
    const float* bff2   = (const float*)d_in[19];
    const float* Wih0   = (const float*)d_in[20];
    const float* Whh0   = (const float*)d_in[21];
    const float* b0     = (const float*)d_in[22];
    const float* Wih12  = (const float*)d_in[23];
    const float* Whh12  = (const float*)d_in[24];
    const float* b12    = (const float*)d_in[25];
    const float* fc_w   = (const float*)d_in[26];
    const float* fc_b   = (const float*)d_in[27];

    float* ph  = sym_f(g_h);
    float* py  = sym_f(g_y);
    float* pq  = sym_f(g_q);
    float* pk  = sym_f(g_k);
    float* pv  = sym_f(g_v);
    float* po  = sym_f(g_o);
    float* pff = sym_f(g_ff);
    float* pqp = sym_f(g_qp);
    float* pkp = sym_f(g_kp);
    float* pT  = sym_f(g_T);
    float* pgi = sym_f(g_gi);
    float* pl0 = sym_f(g_l0);
    float* pl1 = sym_f(g_l1);
    unsigned* pstab = nullptr;
    { void* p = nullptr; cudaGetSymbolAddress(&p, g_stab); pstab = (unsigned*)p; }

    dim3 g256(256/64, TOK/64), g1024(1024/64, TOK/64);
    dim3 gqkv(256/64, TOK/64, 3);
    dim3 gfeat(512, 1, 2);
    dim3 gattn(NCHUNK, 32);

    // input projection
    gemm_kernel<<<g256, 128>>>(x, Win_w, Win_b, nullptr, nullptr, ph, TOK, 256, 128, 0);

    for (int l = 0; l < NLAYERS; l++) {
        const float* prj = proj + (size_t)l*MFEAT*DH;
        ln_kernel<<<TOK/8, 256>>>(ph, ln1_w + l*256, ln1_b + l*256, py, pstab);
        qkv_kernel<<<gqkv, 128>>>(py, Wq + (size_t)l*256*256, Wk + (size_t)l*256*256, Wv + (size_t)l*256*256,
                                  bq + l*256, bk + l*256, bv + l*256, pq, pk, pv);
        feat_kernel<<<gfeat, 128>>>(pq, pk, prj, pqp, pkp, pstab);
        attn_sum_kernel<<<gattn, 256>>>(pkp, pv, pstab, pT);
        attn_scan_kernel<<<gattn, 256>>>(pqp, pkp, pv, pT, po);
        gemm_kernel<<<g256, 128>>>(po, Wo + (size_t)l*256*256, bo + l*256, nullptr, ph, ph, TOK, 256, 256, 0);
        ln_kernel<<<TOK/8, 256>>>(ph, ln2_w + l*256, ln2_b + l*256, py, nullptr);
        gemm_kernel<<<g1024, 128>>>(py, Wff1 + (size_t)l*1024*256, bff1 + l*1024, nullptr, nullptr, pff, TOK, 1024, 256, 1);
        gemm_kernel<<<g256, 128>>>(pff, Wff2 + (size_t)l*256*1024, bff2 + l*256, nullptr, ph, ph, TOK, 256, 1024, 0);
    }

    // ---- BiLSTM layer 0 (input D=256) ----
    gemm_kernel<<<g1024, 128>>>(ph, Wih0,             b0,        b0 + 1024, nullptr, pgi,            TOK, 1024, 256, 0);
    gemm_kernel<<<g1024, 128>>>(ph, Wih0 + 1024*256,  b0 + 2048, b0 + 3072, nullptr, pgi + TOK*1024, TOK, 1024, 256, 0);
    lstm_kernel<<<64, 256>>>(pgi, Whh0, pl0);

    // ---- BiLSTM layers 1,2 (input 2*HID=512) ----
    float* lin = pl0;
    float* lo  = pl1;
    for (int ll = 0; ll < 2; ll++) {
        for (int dir = 0; dir < 2; dir++) {
            const float* wih = Wih12 + (size_t)(ll*2 + dir)*1024*512;
            const float* bb1 = b12 + (size_t)((ll*2 + dir)*2 + 0)*1024;
            const float* bb2 = b12 + (size_t)((ll*2 + dir)*2 + 1)*1024;
            gemm_kernel<<<g1024, 128>>>(lin, wih, bb1, bb2, nullptr, pgi + (size_t)dir*TOK*1024, TOK, 1024, 512, 0);
        }
        lstm_kernel<<<64, 256>>>(pgi, Whh12 + (size_t)ll*2*1024*256, lo);
        float* tmp = lin; lin = lo; lo = tmp;
    }

    // ---- final head ----
    fc_kernel<<<1, 128>>>(lin, fc_w, fc_b, (float*)d_out);
}

// round 13
// speedup vs baseline: 1.1320x; 1.1320x over previous
#include <cuda_runtime.h>
#include <cuda_bf16.h>
#include <cstdint>

// ---------------- model dims ----------------
#define TOK   2048            // B*N = 4*512
#define NSEQ  512
#define BATCH 4
#define DDIM  256
#define HEADS 8
#define DH    32
#define MFEAT 110
#define NLAYERS 8
#define HID   256
#define FFDIM 1024

#define CHUNK  32
#define NCHUNK 16
#define STATE  (MFEAT*33)     // 110 x (32 S-cols + 1 z) = 3630

#define SCALE_Q 0.42044820762685725f   // 32^-0.25
#define MNS     0.09534625892455924f   // 110^-0.5
#define EPS_K   1e-4f
#define EPS_D   1e-6f

// ---------------- scratch (device globals; no runtime alloc) -----------------
__device__ float    g_h  [TOK*DDIM];
__device__ float    g_y  [TOK*DDIM];
__device__ float    g_q  [TOK*DDIM];
__device__ float    g_k  [TOK*DDIM];
__device__ float    g_v  [TOK*DDIM];
__device__ float    g_o  [TOK*DDIM];
__device__ float    g_ff [TOK*FFDIM];
__device__ float    g_qp [32*NSEQ*MFEAT];
__device__ float    g_kp [32*NSEQ*MFEAT];
__device__ unsigned g_stab[32];
__device__ float    g_T  [32*NCHUNK*STATE];     // chunk totals
__device__ float    g_gi [2*TOK*1024];
__device__ float    g_l0 [TOK*512];
__device__ float    g_l1 [TOK*512];

// ---------------- helpers ----------------
__device__ __forceinline__ float wsum(float v) {
    #pragma unroll
    for (int o = 16; o > 0; o >>= 1) v += __shfl_xor_sync(0xffffffffu, v, o);
    return v;
}
__device__ __forceinline__ float wmaxf(float v) {
    #pragma unroll
    for (int o = 16; o > 0; o >>= 1) v = fmaxf(v, __shfl_xor_sync(0xffffffffu, v, o));
    return v;
}
__device__ __forceinline__ unsigned fenc(float f) {
    unsigned u = __float_as_uint(f);
    return (u & 0x80000000u) ? ~u : (u | 0x80000000u);
}
__device__ __forceinline__ float fdec(unsigned e) {
    unsigned u = (e & 0x80000000u) ? (e ^ 0x80000000u) : ~e;
    return __uint_as_float(u);
}
__device__ __forceinline__ float sigm(float x) { return 1.0f / (1.0f + expf(-x)); }

// packed fp32x2 FMA (Blackwell)
__device__ __forceinline__ void ffma2(unsigned long long& c, unsigned long long a, unsigned long long b) {
    asm("fma.rn.f32x2 %0, %1, %2, %3;" : "=l"(c) : "l"(a), "l"(b), "l"(c));
}
__device__ __forceinline__ float f2lo(unsigned long long v) { return __uint_as_float((unsigned)v); }
__device__ __forceinline__ float f2hi(unsigned long long v) { return __uint_as_float((unsigned)(v >> 32)); }

// tf32 helpers
__device__ __forceinline__ unsigned f2tf(float x) {
    unsigned r;
    asm("cvt.rna.tf32.f32 %0, %1;" : "=r"(r) : "f"(x));
    return r;
}
__device__ __forceinline__ void mma_tf32(float c[4], unsigned a0, unsigned a1, unsigned a2, unsigned a3,
                                         unsigned b0, unsigned b1) {
    asm("mma.sync.aligned.m16n8k8.row.col.f32.tf32.tf32.f32 "
        "{%0,%1,%2,%3}, {%4,%5,%6,%7}, {%8,%9}, {%0,%1,%2,%3};"
        : "+f"(c[0]), "+f"(c[1]), "+f"(c[2]), "+f"(c[3])
        : "r"(a0), "r"(a1), "r"(a2), "r"(a3), "r"(b0), "r"(b1));
}

// ---------------- epilogue helper (shared by both GEMM kernels) --------------
__device__ __forceinline__ void gemm_epilogue(float acc[2][4][4],
                                              const float* __restrict__ bias1,
                                              const float* __restrict__ bias2,
                                              const float* __restrict__ res,
                                              float* __restrict__ C,
                                              int N, int act, int m0, int n0,
                                              int mw, int nw, int g, int tg)
{
    #pragma unroll
    for (int mi = 0; mi < 2; mi++) {
        #pragma unroll
        for (int j = 0; j < 4; j++) {
            int col = n0 + nw + 8*j + 2*tg;
            float b1x = 0.f, b1y = 0.f, b2x = 0.f, b2y = 0.f;
            if (bias1) { float2 bv = *(const float2*)(bias1 + col); b1x = bv.x; b1y = bv.y; }
            if (bias2) { float2 bv = *(const float2*)(bias2 + col); b2x = bv.x; b2y = bv.y; }
            #pragma unroll
            for (int half = 0; half < 2; half++) {
                int row = m0 + mw + 16*mi + g + 8*half;
                float v0 = acc[mi][j][2*half+0] + b1x + b2x;
                float v1 = acc[mi][j][2*half+1] + b1y + b2y;
                if (act == 1) {
                    v0 = 0.5f*v0*(1.0f + erff(v0*0.7071067811865476f));
                    v1 = 0.5f*v1*(1.0f + erff(v1*0.7071067811865476f));
                }
                if (res) {
                    float2 rv = *(const float2*)(res + (size_t)row*N + col);
                    v0 += rv.x; v1 += rv.y;
                }
                *(float2*)(C + (size_t)row*N + col) = make_float2(v0, v1);
            }
        }
    }
}

// ---------------- TF32 tensor-core GEMM: C[M,N] = A[M,K] @ W[N,K]^T ----------
// tile 64x64, 128 threads (4 warps), warp tile 32x32, k-stage 16
__device__ __forceinline__ void gemm_tile(const float* __restrict__ A, const float* __restrict__ W,
                                          const float* __restrict__ bias1, const float* __restrict__ bias2,
                                          const float* __restrict__ res, float* __restrict__ C,
                                          int M, int N, int K, int act, int m0, int n0)
{
    __shared__ unsigned As[16][72];
    __shared__ unsigned Ws[16][72];
    int t = threadIdx.x;                 // 128
    int warp = t >> 5, lane = t & 31;
    int mw = (warp & 1) * 32, nw = (warp >> 1) * 32;
    int g = lane >> 2, tg = lane & 3;

    float acc[2][4][4];
    #pragma unroll
    for (int mi = 0; mi < 2; mi++)
        #pragma unroll
        for (int j = 0; j < 4; j++)
            #pragma unroll
            for (int e = 0; e < 4; e++) acc[mi][j][e] = 0.f;

    int lrow = t >> 1, lk8 = (t & 1) * 8;
    const float* Ap = A + (size_t)(m0 + lrow) * K + lk8;
    const float* Wp = W + (size_t)(n0 + lrow) * K + lk8;

    for (int k0 = 0; k0 < K; k0 += 16) {
        float4 av0 = *(const float4*)(Ap + k0);
        float4 av1 = *(const float4*)(Ap + k0 + 4);
        float4 wv0 = *(const float4*)(Wp + k0);
        float4 wv1 = *(const float4*)(Wp + k0 + 4);
        As[lk8+0][lrow] = f2tf(av0.x); As[lk8+1][lrow] = f2tf(av0.y);
        As[lk8+2][lrow] = f2tf(av0.z); As[lk8+3][lrow] = f2tf(av0.w);
        As[lk8+4][lrow] = f2tf(av1.x); As[lk8+5][lrow] = f2tf(av1.y);
        As[lk8+6][lrow] = f2tf(av1.z); As[lk8+7][lrow] = f2tf(av1.w);
        Ws[lk8+0][lrow] = f2tf(wv0.x); Ws[lk8+1][lrow] = f2tf(wv0.y);
        Ws[lk8+2][lrow] = f2tf(wv0.z); Ws[lk8+3][lrow] = f2tf(wv0.w);
        Ws[lk8+4][lrow] = f2tf(wv1.x); Ws[lk8+5][lrow] = f2tf(wv1.y);
        Ws[lk8+6][lrow] = f2tf(wv1.z); Ws[lk8+7][lrow] = f2tf(wv1.w);
        __syncthreads();
        #pragma unroll
        for (int kk = 0; kk < 16; kk += 8) {
            unsigned a[2][4], b[4][2];
            #pragma unroll
            for (int mi = 0; mi < 2; mi++) {
                int mb = mw + 16*mi + g;
                a[mi][0] = As[kk+tg  ][mb];
                a[mi][1] = As[kk+tg  ][mb+8];
                a[mi][2] = As[kk+tg+4][mb];
                a[mi][3] = As[kk+tg+4][mb+8];
            }
            #pragma unroll
            for (int j = 0; j < 4; j++) {
                int nb = nw + 8*j + g;
                b[j][0] = Ws[kk+tg  ][nb];
                b[j][1] = Ws[kk+tg+4][nb];
            }
            #pragma unroll
            for (int mi = 0; mi < 2; mi++)
                #pragma unroll
                for (int j = 0; j < 4; j++)
                    mma_tf32(acc[mi][j], a[mi][0], a[mi][1], a[mi][2], a[mi][3], b[j][0], b[j][1]);
        }
        __syncthreads();
    }

    gemm_epilogue(acc, bias1, bias2, res, C, N, act, m0, n0, mw, nw, g, tg);
}

__global__ void __launch_bounds__(128) gemm_kernel(const float* __restrict__ A, const float* __restrict__ W,
                            const float* __restrict__ bias1, const float* __restrict__ bias2,
                            const float* __restrict__ res, float* __restrict__ C,
                            int M, int N, int K, int act)
{
    gemm_tile(A, W, bias1, bias2, res, C, M, N, K, act, blockIdx.y*64, blockIdx.x*64);
}

__global__ void __launch_bounds__(128) qkv_kernel(const float* __restrict__ A,
                           const float* __restrict__ Wq_, const float* __restrict__ Wk_, const float* __restrict__ Wv_,
                           const float* __restrict__ bq_, const float* __restrict__ bk_, const float* __restrict__ bv_,
                           float* __restrict__ Cq, float* __restrict__ Ck, float* __restrict__ Cv)
{
    int z = blockIdx.z;
    const float* W = (z == 0) ? Wq_ : (z == 1) ? Wk_ : Wv_;
    const float* b = (z == 0) ? bq_ : (z == 1) ? bk_ : bv_;
    float*       C = (z == 0) ? Cq  : (z == 1) ? Ck  : Cv;
    gemm_tile(A, W, b, nullptr, nullptr, C, TOK, 256, 256, 0, blockIdx.y*64, blockIdx.x*64);
}

// ---------------- split-K=2 GEMM for grid-limited (128-CTA) GEMMs ------------
// 256 threads: warps 0-3 do K[0,K/2), warps 4-7 do K[K/2,K); smem reduction.
__global__ void __launch_bounds__(256) gemm_sk_kernel(const float* __restrict__ A, const float* __restrict__ W,
                            const float* __restrict__ bias1, const float* __restrict__ bias2,
                            const float* __restrict__ res, float* __restrict__ C,
                            int M, int N, int K, int act)
{
    __shared__ unsigned As[2][16][72];
    __shared__ unsigned Ws[2][16][72];
    __shared__ float red[64][66];
    int m0 = blockIdx.y*64, n0 = blockIdx.x*64;
    int t = threadIdx.x;                 // 256
    int warp = t >> 5, lane = t & 31;
    int kg = warp >> 2;                  // k-group 0/1
    int w4 = warp & 3;
    int mw = (w4 & 1) * 32, nw = (w4 >> 1) * 32;
    int g = lane >> 2, tg = lane & 3;

    float acc[2][4][4];
    #pragma unroll
    for (int mi = 0; mi < 2; mi++)
        #pragma unroll
        for (int j = 0; j < 4; j++)
            #pragma unroll
            for (int e = 0; e < 4; e++) acc[mi][j][e] = 0.f;

    int tt = t & 127;
    int lrow = tt >> 1, lk8 = (tt & 1) * 8;
    int Kh = K >> 1;
    const float* Ap = A + (size_t)(m0 + lrow) * K + (size_t)kg*Kh + lk8;
    const float* Wp = W + (size_t)(n0 + lrow) * K + (size_t)kg*Kh + lk8;

    for (int k0 = 0; k0 < Kh; k0 += 16) {
        float4 av0 = *(const float4*)(Ap + k0);
        float4 av1 = *(const float4*)(Ap + k0 + 4);
        float4 wv0 = *(const float4*)(Wp + k0);
        float4 wv1 = *(const float4*)(Wp + k0 + 4);
        As[kg][lk8+0][lrow] = f2tf(av0.x); As[kg][lk8+1][lrow] = f2tf(av0.y);
        As[kg][lk8+2][lrow] = f2tf(av0.z); As[kg][lk8+3][lrow] = f2tf(av0.w);
        As[kg][lk8+4][lrow] = f2tf(av1.x); As[kg][lk8+5][lrow] = f2tf(av1.y);
        As[kg][lk8+6][lrow] = f2tf(av1.z); As[kg][lk8+7][lrow] = f2tf(av1.w);
        Ws[kg][lk8+0][lrow] = f2tf(wv0.x); Ws[kg][lk8+1][lrow] = f2tf(wv0.y);
        Ws[kg][lk8+2][lrow] = f2tf(wv0.z); Ws[kg][lk8+3][lrow] = f2tf(wv0.w);
        Ws[kg][lk8+4][lrow] = f2tf(wv1.x); Ws[kg][lk8+5][lrow] = f2tf(wv1.y);
        Ws[kg][lk8+6][lrow] = f2tf(wv1.z); Ws[kg][lk8+7][lrow] = f2tf(wv1.w);
        __syncthreads();
        #pragma unroll
        for (int kk = 0; kk < 16; kk += 8) {
            unsigned a[2][4], b[4][2];
            #pragma unroll
            for (int mi = 0; mi < 2; mi++) {
                int mb = mw + 16*mi + g;
                a[mi][0] = As[kg][kk+tg  ][mb];
                a[mi][1] = As[kg][kk+tg  ][mb+8];
                a[mi][2] = As[kg][kk+tg+4][mb];
                a[mi][3] = As[kg][kk+tg+4][mb+8];
            }
            #pragma unroll
            for (int j = 0; j < 4; j++) {
                int nb = nw + 8*j + g;
                b[j][0] = Ws[kg][kk+tg  ][nb];
                b[j][1] = Ws[kg][kk+tg+4][nb];
            }
            #pragma unroll
            for (int mi = 0; mi < 2; mi++)
                #pragma unroll
                for (int j = 0; j < 4; j++)
                    mma_tf32(acc[mi][j], a[mi][0], a[mi][1], a[mi][2], a[mi][3], b[j][0], b[j][1]);
        }
        __syncthreads();
    }

    // reduce group 1 into group 0
    if (kg == 1) {
        #pragma unroll
        for (int mi = 0; mi < 2; mi++)
            #pragma unroll
            for (int j = 0; j < 4; j++)
                #pragma unroll
                for (int half = 0; half < 2; half++) {
                    int row = mw + 16*mi + g + 8*half;
                    int col = nw + 8*j + 2*tg;
                    red[row][col]   = acc[mi][j][2*half+0];
                    red[row][col+1] = acc[mi][j][2*half+1];
                }
    }
    __syncthreads();
    if (kg == 0) {
        #pragma unroll
        for (int mi = 0; mi < 2; mi++)
            #pragma unroll
            for (int j = 0; j < 4; j++)
                #pragma unroll
                for (int half = 0; half < 2; half++) {
                    int row = mw + 16*mi + g + 8*half;
                    int col = nw + 8*j + 2*tg;
                    acc[mi][j][2*half+0] += red[row][col];
                    acc[mi][j][2*half+1] += red[row][col+1];
                }
        gemm_epilogue(acc, bias1, bias2, res, C, N, act, m0, n0, mw, nw, g, tg);
    }
}

// ---------------- layernorm: one warp per row, 8 rows per block --------------
__global__ void __launch_bounds__(256) ln_kernel(const float* __restrict__ x, const float* __restrict__ w,
                          const float* __restrict__ b, float* __restrict__ y,
                          unsigned* __restrict__ stab)
{
    int t = threadIdx.x;
    if (stab && blockIdx.x == 0 && t < 32) stab[t] = 0x007FFFFFu;
    int warp = t >> 5, lane = t & 31;
    int row = blockIdx.x*8 + warp;
    const float* xr = x + (size_t)row*256;
    float v[8];
    float s1 = 0.f, s2 = 0.f;
    #pragma unroll
    for (int j = 0; j < 8; j++) {
        v[j] = xr[lane + 32*j];
        s1 += v[j];
        s2 += v[j]*v[j];
    }
    s1 = wsum(s1);
    s2 = wsum(s2);
    float mu = s1 * (1.0f/256.0f);
    float ri = rsqrtf(s2*(1.0f/256.0f) - mu*mu + 1e-5f);
    float* yr = y + (size_t)row*256;
    #pragma unroll
    for (int j = 0; j < 8; j++) {
        int col = lane + 32*j;
        yr[col] = (v[j] - mu)*ri*w[col] + b[col];
    }
}

// ---------------- FAVOR+ features, merged q/k via blockIdx.z, 4 rows/warp ----
__global__ void __launch_bounds__(128) feat_kernel(const float* __restrict__ qin, const float* __restrict__ kin,
                            const float* __restrict__ proj,
                            float* __restrict__ qp, float* __restrict__ kp,
                            unsigned* __restrict__ stab)
{
    int mode = blockIdx.z;                // 0 = query, 1 = key
    const float* qk = mode ? kin : qin;
    float* out = mode ? kp : qp;
    __shared__ float proj_s[110*33];
    int t = threadIdx.x;   // 128
    for (int i = t; i < 110*33; i += 128) {
        int m = i / 33, d = i - m*33;
        proj_s[i] = (d < 32) ? proj[m*32 + d] : 0.f;
    }
    __syncthreads();
    int warp = t >> 5, lane = t & 31;
    int row0 = blockIdx.x * 32;           // 32 rows per block
    for (int rr = warp*4; rr < 32; rr += 16) {
        float xd[4], dd[4][4];
        #pragma unroll
        for (int q = 0; q < 4; q++) {
            int row = row0 + rr + q;
            int bh = row >> 9, n = row & 511;
            xd[q] = qk[(size_t)((bh >> 3)*512 + n)*256 + (bh & 7)*32 + lane] * SCALE_Q;
            #pragma unroll
            for (int mb = 0; mb < 4; mb++) dd[q][mb] = 0.f;
        }
        #pragma unroll
        for (int d = 0; d < 32; d++) {
            float xv[4];
            #pragma unroll
            for (int q = 0; q < 4; q++) xv[q] = __shfl_sync(0xffffffffu, xd[q], d);
            float p0 = proj_s[lane*33 + d];
            float p1 = proj_s[(lane+32)*33 + d];
            float p2 = proj_s[(lane+64)*33 + d];
            #pragma unroll
            for (int q = 0; q < 4; q++) {
                dd[q][0] += xv[q]*p0;
                dd[q][1] += xv[q]*p1;
                dd[q][2] += xv[q]*p2;
            }
            if (lane < 14) {
                float p3 = proj_s[(lane+96)*33 + d];
                #pragma unroll
                for (int q = 0; q < 4; q++) dd[q][3] += xv[q]*p3;
            }
        }
        #pragma unroll
        for (int q = 0; q < 4; q++) {
            int row = row0 + rr + q;
            int bh = row >> 9;
            float diag = 0.5f * wsum(xd[q]*xd[q]);
            float mx = fmaxf(fmaxf(dd[q][0], dd[q][1]), dd[q][2]);
            if (lane < 14) mx = fmaxf(mx, dd[q][3]);
            mx = wmaxf(mx);
            float* orow = out + (size_t)row*MFEAT;
            if (mode) {
                orow[lane]      = dd[q][0] - diag;
                orow[lane+32]   = dd[q][1] - diag;
                orow[lane+64]   = dd[q][2] - diag;
                if (lane < 14) orow[lane+96] = dd[q][3] - diag;
                if (lane == 0) atomicMax(&stab[bh], fenc(mx));
            } else {
                orow[lane]      = MNS*(expf(dd[q][0] - diag - mx) + EPS_K);
                orow[lane+32]   = MNS*(expf(dd[q][1] - diag - mx) + EPS_K);
                orow[lane+64]   = MNS*(expf(dd[q][2] - diag - mx) + EPS_K);
                if (lane < 14) orow[lane+96] = MNS*(expf(dd[q][3] - diag - mx) + EPS_K);
            }
        }
    }
}

// ---------------- attention pass 1: normalize kp + per-chunk totals ----------
__global__ void attn_sum_kernel(float* __restrict__ kp, const float* __restrict__ v,
                                const unsigned* __restrict__ stab, float* __restrict__ T)
{
    __shared__ float kp_c[CHUNK*MFEAT];
    __shared__ float v_c [CHUNK*32];
    int ch = blockIdx.x, bh = blockIdx.y;
    int b = bh >> 3, h = bh & 7;
    int t = threadIdx.x;                 // 256
    float stv = fdec(stab[bh]);
    float* kpb = kp + (size_t)bh*NSEQ*MFEAT + (size_t)ch*CHUNK*MFEAT;
    for (int i = t; i < CHUNK*MFEAT; i += 256) {
        float e = MNS*(expf(kpb[i] - stv) + EPS_K);
        kp_c[i] = e;
        kpb[i] = e;                      // normalized for attn_scan
    }
    for (int i = t; i < CHUNK*32; i += 256) {
        int n = i >> 5, d = i & 31;
        v_c[i] = v[(size_t)(b*512 + ch*CHUNK + n)*256 + h*32 + d];
    }
    __syncthreads();

    int mg = t >> 5, d = t & 31;
    float S[14];
    #pragma unroll
    for (int j = 0; j < 14; j++) S[j] = 0.f;
    for (int n = 0; n < CHUNK; n++) {
        float vd = v_c[n*32 + d];
        #pragma unroll
        for (int j = 0; j < 14; j++) {
            int m = mg + 8*j;
            if (m < MFEAT) S[j] += kp_c[n*MFEAT + m]*vd;
        }
    }
    float* Tb = T + (size_t)(bh*NCHUNK + ch)*STATE;
    #pragma unroll
    for (int j = 0; j < 14; j++) {
        int m = mg + 8*j;
        if (m < MFEAT) Tb[m*33 + d] = S[j];
    }
    if (t < MFEAT) {
        float z = 0.f;
        for (int n = 0; n < CHUNK; n++) z += kp_c[n*MFEAT + t];
        Tb[t*33 + 32] = z;
    }
}

// ---------------- attention pass 2: within-chunk scan, double-buffered -------
__global__ void attn_scan_kernel(const float* __restrict__ qp, const float* __restrict__ kp,
                                 const float* __restrict__ v, const float* __restrict__ T,
                                 float* __restrict__ o)
{
    __shared__ float kp_c[CHUNK*MFEAT];
    __shared__ float qp_c[CHUNK*MFEAT];
    __shared__ float v_c [CHUNK*32];
    __shared__ float qz_s[2][MFEAT];
    __shared__ float part_s[2][8][33];
    int ch = blockIdx.x, bh = blockIdx.y;
    int b = bh >> 3, h = bh & 7;
    int t = threadIdx.x;                 // 256
    const float* kpb = kp + (size_t)bh*NSEQ*MFEAT + (size_t)ch*CHUNK*MFEAT;
    const float* qpb = qp + (size_t)bh*NSEQ*MFEAT + (size_t)ch*CHUNK*MFEAT;
    for (int i = t; i < CHUNK*MFEAT; i += 256) { kp_c[i] = kpb[i]; qp_c[i] = qpb[i]; }
    for (int i = t; i < CHUNK*32; i += 256) {
        int n = i >> 5, d = i & 31;
        v_c[i] = v[(size_t)(b*512 + ch*CHUNK + n)*256 + h*32 + d];
    }
    int mg = t >> 5, d = t & 31;
    // inline exclusive prefix over earlier chunks (same summation order)
    float S[14];
    #pragma unroll
    for (int j = 0; j < 14; j++) S[j] = 0.f;
    float z = 0.f;
    for (int c = 0; c < ch; c++) {
        const float* Tc = T + (size_t)(bh*NCHUNK + c)*STATE;
        #pragma unroll
        for (int j = 0; j < 14; j++) {
            int m = mg + 8*j;
            if (m < MFEAT) S[j] += Tc[m*33 + d];
        }
        if (t < MFEAT) z += Tc[t*33 + 32];
    }
    __syncthreads();

    for (int n = 0; n < CHUNK; n++) {
        int pb = n & 1;
        if (t < MFEAT) { z += kp_c[n*MFEAT + t]; qz_s[pb][t] = qp_c[n*MFEAT + t]*z; }
        float vd = v_c[n*32 + d];
        float acc = 0.f;
        #pragma unroll
        for (int j = 0; j < 14; j++) {
            int m = mg + 8*j;
            if (m < MFEAT) {
                S[j] += kp_c[n*MFEAT + m]*vd;
                acc  += qp_c[n*MFEAT + m]*S[j];
            }
        }
        part_s[pb][mg][d] = acc;
        __syncthreads();
        if (t < 32) {
            float qs = qz_s[pb][t] + qz_s[pb][t+32] + qz_s[pb][t+64] + ((t < 14) ? qz_s[pb][t+96] : 0.f);
            float denom = wsum(qs) + EPS_D;
            float s = 0.f;
            #pragma unroll
            for (int g = 0; g < 8; g++) s += part_s[pb][g][t];
            o[(size_t)(b*512 + ch*CHUNK + n)*256 + h*32 + t] = s / denom;
        }
        // no trailing sync: next iter writes the other buffer
    }
}

// ---------------- BiLSTM scan: 8-CTA cluster, st.async mbarrier handshake ----
// (2846-us proven version: part_s reduction, 4 ffma2 chains, half = t>>7)
__global__ void __cluster_dims__(8,1,1) __launch_bounds__(256,1)
lstm_kernel(const float* __restrict__ gi,      // [2][2048][1024] dir-major
            const float* __restrict__ whh,     // [2][1024][256]  dir-major
            float* __restrict__ out)           // [2048][512]
{
    __shared__ __align__(16) float h_buf[512];
    __shared__ float part_s[256];
    __shared__ float gates_s[128];
    __shared__ __align__(16) unsigned long long mbar[2];

    int t   = threadIdx.x;              // 256
    int cta = blockIdx.x;
    int r   = cta & 7;
    int s   = cta >> 3;
    int b   = s >> 1, dir = s & 1;

    const float* whh_d = whh + (size_t)dir*1024*256;
    const float* gi_d  = gi  + (size_t)dir*TOK*1024 + (size_t)b*512*1024;

    int half = t >> 7, row = t & 127;
    int gate = row >> 5, jl = row & 31;
    const float* wp = whh_d + (size_t)(gate*256 + 32*r + jl)*256 + 128*half;

    unsigned long long w2[64];
    #pragma unroll
    for (int c = 0; c < 32; c++) {
        ulonglong2 u = *(const ulonglong2*)(wp + 4*c);
        w2[2*c]   = u.x;
        w2[2*c+1] = u.y;
    }

    h_buf[t] = 0.f;
    h_buf[256 + t] = 0.f;
    uint32_t hb = (uint32_t)__cvta_generic_to_shared(h_buf);
    uint32_t mb = (uint32_t)__cvta_generic_to_shared(mbar);
    if (t == 0) {
        asm volatile("mbarrier.init.shared.b64 [%0], 1;" :: "r"(mb)     : "memory");
        asm volatile("mbarrier.init.shared.b64 [%0], 1;" :: "r"(mb + 8) : "memory");
    }
    float c_reg = 0.f;
    int gidx = ((t >> 5) << 8) + 32*r + (t & 31);   // valid for t<128
    __syncthreads();
    asm volatile("barrier.cluster.arrive.aligned;\n\tbarrier.cluster.wait.aligned;" ::: "memory");

    uint32_t peer_base[8];
    if (t < 32) {
        #pragma unroll
        for (int p = 0; p < 8; p++) {
            uint32_t pb;
            asm volatile("mapa.shared::cluster.u32 %0, %1, %2;" : "=r"(pb) : "r"(hb), "r"(p));
            peer_base[p] = pb;
        }
    }
    uint32_t mb_off = mb - hb;

    float pg = 0.f;
    if (t < 128) pg = gi_d[(size_t)(dir ? 511 : 0)*1024 + gidx];

    int par0 = 0, par1 = 0;
    for (int step = 0; step < 512; step++) {
        int mi = step & 1;
        if (step > 0) {
            uint32_t ma = mb + mi*8;
            int ph = mi ? par1 : par0;
            unsigned done;
            asm volatile(
                "{\n\t.reg .pred p;\n\t"
                "mbarrier.try_wait.parity.acquire.cta.shared::cta.b64 p, [%1], %2;\n\t"
                "selp.b32 %0, 1, 0, p;\n\t}"
                : "=r"(done) : "r"(ma), "r"(ph) : "memory");
            if (!done) {
                asm volatile(
                    "{\n\t.reg .pred P1;\n\t"
                    "WL_%=:\n\t"
                    "mbarrier.try_wait.parity.acquire.cta.shared::cta.b64 P1, [%0], %1, 0x989680;\n\t"
                    "@P1 bra.uni WD_%=;\n\t"
                    "bra.uni WL_%=;\n\t"
                    "WD_%=:\n\t}"
                    :: "r"(ma), "r"(ph) : "memory");
            }
            if (mi) par1 ^= 1; else par0 ^= 1;
        }
        if (t == 0 && step + 1 < 512) {
            uint32_t ma = mb + (mi ^ 1)*8;
            asm volatile("mbarrier.arrive.expect_tx.shared.b64 _, [%0], %1;"
                         :: "r"(ma), "r"(1024) : "memory");
        }
        int n = dir ? (511 - step) : step;
        const float* hr = h_buf + mi*256 + 128*half;
        unsigned long long a0 = 0ull, a1 = 0ull, a2 = 0ull, a3 = 0ull;
        #pragma unroll
        for (int c = 0; c < 16; c++) {
            ulonglong2 h0 = *(const ulonglong2*)(hr + 8*c);
            ulonglong2 h1 = *(const ulonglong2*)(hr + 8*c + 4);
            ffma2(a0, w2[4*c+0], h0.x);
            ffma2(a1, w2[4*c+1], h0.y);
            ffma2(a2, w2[4*c+2], h1.x);
            ffma2(a3, w2[4*c+3], h1.y);
        }
        part_s[half*128 + row] = (f2lo(a0) + f2hi(a0)) + (f2lo(a1) + f2hi(a1))
                               + (f2lo(a2) + f2hi(a2)) + (f2lo(a3) + f2hi(a3));
        __syncthreads();
        if (t < 128) {
            gates_s[t] = pg + part_s[t] + part_s[128 + t];
            if (step + 1 < 512)
                pg = gi_d[(size_t)(dir ? (510 - step) : (step + 1))*1024 + gidx];
        }
        __syncthreads();
        if (t < 32) {
            float ig = gates_s[t], fg = gates_s[32+t], gg = gates_s[64+t], og = gates_s[96+t];
            c_reg = sigm(fg)*c_reg + sigm(ig)*tanhf(gg);
            float hval = sigm(og)*tanhf(c_reg);
            out[(size_t)(b*512 + n)*512 + dir*256 + 32*r + t] = hval;
            if (step + 1 < 512) {
                uint32_t off_h = (uint32_t)((((mi ^ 1)*256) + 32*r + t) << 2);
                uint32_t rm_off = mb_off + (uint32_t)((mi ^ 1)*8);
                unsigned hv = __float_as_uint(hval);
                #pragma unroll
                for (int p = 0; p < 8; p++) {
                    uint32_t ra = peer_base[p] + off_h;
                    uint32_t rm = peer_base[p] + rm_off;
                    asm volatile("st.async.shared::cluster.mbarrier::complete_tx::bytes.b32 [%0], %1, [%2];"
                                 :: "r"(ra), "r"(hv), "r"(rm) : "memory");
                }
            }
        }
    }
}

// ---------------- final head ----------------
__global__ void fc_kernel(const float* __restrict__ hin, const float* __restrict__ fw,
                          const float* __restrict__ fb, float* __restrict__ outp)
{
    int t = threadIdx.x;           // 128
    int warp = t >> 5, lane = t & 31;
    const float* rowp = hin + (size_t)(warp*512 + 511)*512;
    float s = 0.f;
    for (int j = lane; j < 512; j += 32) s += rowp[j]*fw[j];
    s = wsum(s);
    if (lane == 0) outp[warp] = s + fb[0];
}

// ---------------- launch ----------------
static float* sym_f(const void* s) { void* p = nullptr; cudaGetSymbolAddress(&p, s); return (float*)p; }

extern "C" void kernel_launch(void* const* d_in, const int* in_sizes, int n_in,
                              void* d_out, int out_size)
{
    (void)in_sizes; (void)n_in; (void)out_size;
    const float* x      = (const float*)d_in[0];
    const float* Win_w  = (const float*)d_in[1];
    const float* Win_b  = (const float*)d_in[2];
    const float* ln1_w  = (const float*)d_in[3];
    const float* ln1_b  = (const float*)d_in[4];
    const float* Wq     = (const float*)d_in[5];
    const float* bq     = (const float*)d_in[6];
    const float* Wk     = (const float*)d_in[7];
    const float* bk     = (const float*)d_in[8];
    const float* Wv     = (const float*)d_in[9];
    const float* bv     = (const float*)d_in[10];
    const float* Wo     = (const float*)d_in[11];
    const float* bo     = (const float*)d_in[12];
    const float* proj   = (const float*)d_in[13];
    const float* ln2_w  = (const float*)d_in[14];
    const float* ln2_b  = (const float*)d_in[15];
    const float* Wff1   = (const float*)d_in[16];
    const float* bff1   = (const float*)d_in[17];
    const float* Wff2   = (const float*)d_in[18];
    const float* bff2   = (const float*)d_in[19];
    const float* Wih0   = (const float*)d_in[20];
    const float* Whh0   = (const float*)d_in[21];
    const float* b0     = (const float*)d_in[22];
    const float* Wih12  = (const float*)d_in[23];
    const float* Whh12  = (const float*)d_in[24];
    const float* b12    = (const float*)d_in[25];
    const float* fc_w   = (const float*)d_in[26];
    const float* fc_b   = (const float*)d_in[27];

    float* ph  = sym_f(g_h);
    float* py  = sym_f(g_y);
    float* pq  = sym_f(g_q);
    float* pk  = sym_f(g_k);
    float* pv  = sym_f(g_v);
    float* po  = sym_f(g_o);
    float* pff = sym_f(g_ff);
    float* pqp = sym_f(g_qp);
    float* pkp = sym_f(g_kp);
    float* pT  = sym_f(g_T);
    float* pgi = sym_f(g_gi);
    float* pl0 = sym_f(g_l0);
    float* pl1 = sym_f(g_l1);
    unsigned* pstab = nullptr;
    { void* p = nullptr; cudaGetSymbolAddress(&p, g_stab); pstab = (unsigned*)p; }

    dim3 g256(256/64, TOK/64), g1024(1024/64, TOK/64);
    dim3 gqkv(256/64, TOK/64, 3);
    dim3 gfeat(512, 1, 2);
    dim3 gattn(NCHUNK, 32);

    // input projection (split-K: grid 128 only)
    gemm_sk_kernel<<<g256, 256>>>(x, Win_w, Win_b, nullptr, nullptr, ph, TOK, 256, 128, 0);

    for (int l = 0; l < NLAYERS; l++) {
        const float* prj = proj + (size_t)l*MFEAT*DH;
        ln_kernel<<<TOK/8, 256>>>(ph, ln1_w + l*256, ln1_b + l*256, py, pstab);
        qkv_kernel<<<gqkv, 128>>>(py, Wq + (size_t)l*256*256, Wk + (size_t)l*256*256, Wv + (size_t)l*256*256,
                                  bq + l*256, bk + l*256, bv + l*256, pq, pk, pv);
        feat_kernel<<<gfeat, 128>>>(pq, pk, prj, pqp, pkp, pstab);
        attn_sum_kernel<<<gattn, 256>>>(pkp, pv, pstab, pT);
        attn_scan_kernel<<<gattn, 256>>>(pqp, pkp, pv, pT, po);
        gemm_sk_kernel<<<g256, 256>>>(po, Wo + (size_t)l*256*256, bo + l*256, nullptr, ph, ph, TOK, 256, 256, 0);
        ln_kernel<<<TOK/8, 256>>>(ph, ln2_w + l*256, ln2_b + l*256, py, nullptr);
        gemm_kernel<<<g1024, 128>>>(py, Wff1 + (size_t)l*1024*256, bff1 + l*1024, nullptr, nullptr, pff, TOK, 1024, 256, 1);
        gemm_sk_kernel<<<g256, 256>>>(pff, Wff2 + (size_t)l*256*1024, bff2 + l*256, nullptr, ph, ph, TOK, 256, 1024, 0);
    }

    // ---- BiLSTM layer 0 (input D=256) ----
    gemm_kernel<<<g1024, 128>>>(ph, Wih0,             b0,        b0 + 1024, nullptr, pgi,            TOK, 1024, 256, 0);
    gemm_kernel<<<g1024, 128>>>(ph, Wih0 + 1024*256,  b0 + 2048, b0 + 3072, nullptr, pgi + TOK*1024, TOK, 1024, 256, 0);
    lstm_kernel<<<64, 256>>>(pgi, Whh0, pl0);

    // ---- BiLSTM layers 1,2 (input 2*HID=512) ----
    float* lin = pl0;
    float* lo  = pl1;
    for (int ll = 0; ll < 2; ll++) {
        for (int dir = 0; dir < 2; dir++) {
            const float* wih = Wih12 + (size_t)(ll*2 + dir)*1024*512;
            const float* bb1 = b12 + (size_t)((ll*2 + dir)*2 + 0)*1024;
            const float* bb2 = b12 + (size_t)((ll*2 + dir)*2 + 1)*1024;
            gemm_kernel<<<g1024, 128>>>(lin, wih, bb1, bb2, nullptr, pgi + (size_t)dir*TOK*1024, TOK, 1024, 512, 0);
        }
        lstm_kernel<<<64, 256>>>(pgi, Whh12 + (size_t)ll*2*1024*256, lo);
        float* tmp = lin; lin = lo; lo = tmp;
    }

    // ---- final head ----
    fc_kernel<<<1, 128>>>(lin, fc_w, fc_b, (float*)d_out);
}

// round 14
// speedup vs baseline: 1.1473x; 1.0135x over previous
#include <cuda_runtime.h>
#include <cuda_bf16.h>
#include <cstdint>

// ---------------- model dims ----------------
#define TOK   2048            // B*N = 4*512
#define NSEQ  512
#define BATCH 4
#define DDIM  256
#define HEADS 8
#define DH    32
#define MFEAT 110
#define NLAYERS 8
#define HID   256
#define FFDIM 1024

#define CHUNK  32
#define NCHUNK 16
#define STATE  (MFEAT*33)     // 110 x (32 S-cols + 1 z) = 3630

#define SCALE_Q 0.42044820762685725f   // 32^-0.25
#define MNS     0.09534625892455924f   // 110^-0.5
#define EPS_K   1e-4f
#define EPS_D   1e-6f

// ---------------- scratch (device globals; no runtime alloc) -----------------
__device__ float    g_h  [TOK*DDIM];
__device__ float    g_y  [TOK*DDIM];
__device__ float    g_q  [TOK*DDIM];
__device__ float    g_k  [TOK*DDIM];
__device__ float    g_v  [TOK*DDIM];
__device__ float    g_o  [TOK*DDIM];
__device__ float    g_ff [TOK*FFDIM];
__device__ float    g_qp [32*NSEQ*MFEAT];
__device__ float    g_kp [32*NSEQ*MFEAT];
__device__ unsigned g_stab[32];
__device__ float    g_T  [32*NCHUNK*STATE];     // chunk totals
__device__ float    g_gi [2*TOK*1024];
__device__ float    g_l0 [TOK*512];
__device__ float    g_l1 [TOK*512];

// ---------------- helpers ----------------
__device__ __forceinline__ float wsum(float v) {
    #pragma unroll
    for (int o = 16; o > 0; o >>= 1) v += __shfl_xor_sync(0xffffffffu, v, o);
    return v;
}
__device__ __forceinline__ float wmaxf(float v) {
    #pragma unroll
    for (int o = 16; o > 0; o >>= 1) v = fmaxf(v, __shfl_xor_sync(0xffffffffu, v, o));
    return v;
}
__device__ __forceinline__ unsigned fenc(float f) {
    unsigned u = __float_as_uint(f);
    return (u & 0x80000000u) ? ~u : (u | 0x80000000u);
}
__device__ __forceinline__ float fdec(unsigned e) {
    unsigned u = (e & 0x80000000u) ? (e ^ 0x80000000u) : ~e;
    return __uint_as_float(u);
}
__device__ __forceinline__ float sigm(float x) { return 1.0f / (1.0f + expf(-x)); }

// packed fp32x2 FMA (Blackwell)
__device__ __forceinline__ void ffma2(unsigned long long& c, unsigned long long a, unsigned long long b) {
    asm("fma.rn.f32x2 %0, %1, %2, %3;" : "=l"(c) : "l"(a), "l"(b), "l"(c));
}
__device__ __forceinline__ float f2lo(unsigned long long v) { return __uint_as_float((unsigned)v); }
__device__ __forceinline__ float f2hi(unsigned long long v) { return __uint_as_float((unsigned)(v >> 32)); }

// tf32 helpers
__device__ __forceinline__ unsigned f2tf(float x) {
    unsigned r;
    asm("cvt.rna.tf32.f32 %0, %1;" : "=r"(r) : "f"(x));
    return r;
}
__device__ __forceinline__ void mma_tf32(float c[4], unsigned a0, unsigned a1, unsigned a2, unsigned a3,
                                         unsigned b0, unsigned b1) {
    asm("mma.sync.aligned.m16n8k8.row.col.f32.tf32.tf32.f32 "
        "{%0,%1,%2,%3}, {%4,%5,%6,%7}, {%8,%9}, {%0,%1,%2,%3};"
        : "+f"(c[0]), "+f"(c[1]), "+f"(c[2]), "+f"(c[3])
        : "r"(a0), "r"(a1), "r"(a2), "r"(a3), "r"(b0), "r"(b1));
}

// ---------------- epilogue helper (shared by GEMM kernels) -------------------
__device__ __forceinline__ void gemm_epilogue(float acc[2][4][4],
                                              const float* __restrict__ bias1,
                                              const float* __restrict__ bias2,
                                              const float* __restrict__ res,
                                              float* __restrict__ C,
                                              int N, int act, int m0, int n0,
                                              int mw, int nw, int g, int tg)
{
    #pragma unroll
    for (int mi = 0; mi < 2; mi++) {
        #pragma unroll
        for (int j = 0; j < 4; j++) {
            int col = n0 + nw + 8*j + 2*tg;
            float b1x = 0.f, b1y = 0.f, b2x = 0.f, b2y = 0.f;
            if (bias1) { float2 bv = *(const float2*)(bias1 + col); b1x = bv.x; b1y = bv.y; }
            if (bias2) { float2 bv = *(const float2*)(bias2 + col); b2x = bv.x; b2y = bv.y; }
            #pragma unroll
            for (int half = 0; half < 2; half++) {
                int row = m0 + mw + 16*mi + g + 8*half;
                float v0 = acc[mi][j][2*half+0] + b1x + b2x;
                float v1 = acc[mi][j][2*half+1] + b1y + b2y;
                if (act == 1) {
                    v0 = 0.5f*v0*(1.0f + erff(v0*0.7071067811865476f));
                    v1 = 0.5f*v1*(1.0f + erff(v1*0.7071067811865476f));
                }
                if (res) {
                    float2 rv = *(const float2*)(res + (size_t)row*N + col);
                    v0 += rv.x; v1 += rv.y;
                }
                *(float2*)(C + (size_t)row*N + col) = make_float2(v0, v1);
            }
        }
    }
}

// ---------------- TF32 tensor-core GEMM: C[M,N] = A[M,K] @ W[N,K]^T ----------
// tile 64x64, 128 threads (4 warps), warp tile 32x32, k-stage 32 (8 LDG/thread
// in flight per stage, half the syncs of the k16 version; k order identical)
__device__ __forceinline__ void gemm_tile(const float* __restrict__ A, const float* __restrict__ W,
                                          const float* __restrict__ bias1, const float* __restrict__ bias2,
                                          const float* __restrict__ res, float* __restrict__ C,
                                          int M, int N, int K, int act, int m0, int n0)
{
    __shared__ unsigned As[32][72];
    __shared__ unsigned Ws[32][72];
    int t = threadIdx.x;                 // 128
    int warp = t >> 5, lane = t & 31;
    int mw = (warp & 1) * 32, nw = (warp >> 1) * 32;
    int g = lane >> 2, tg = lane & 3;

    float acc[2][4][4];
    #pragma unroll
    for (int mi = 0; mi < 2; mi++)
        #pragma unroll
        for (int j = 0; j < 4; j++)
            #pragma unroll
            for (int e = 0; e < 4; e++) acc[mi][j][e] = 0.f;

    int lrow = t >> 1, lk16 = (t & 1) * 16;
    const float* Ap = A + (size_t)(m0 + lrow) * K + lk16;
    const float* Wp = W + (size_t)(n0 + lrow) * K + lk16;

    for (int k0 = 0; k0 < K; k0 += 32) {
        float4 av[4], wv[4];
        #pragma unroll
        for (int i = 0; i < 4; i++) {
            av[i] = *(const float4*)(Ap + k0 + 4*i);
            wv[i] = *(const float4*)(Wp + k0 + 4*i);
        }
        #pragma unroll
        for (int i = 0; i < 4; i++) {
            As[lk16+4*i+0][lrow] = f2tf(av[i].x);
            As[lk16+4*i+1][lrow] = f2tf(av[i].y);
            As[lk16+4*i+2][lrow] = f2tf(av[i].z);
            As[lk16+4*i+3][lrow] = f2tf(av[i].w);
            Ws[lk16+4*i+0][lrow] = f2tf(wv[i].x);
            Ws[lk16+4*i+1][lrow] = f2tf(wv[i].y);
            Ws[lk16+4*i+2][lrow] = f2tf(wv[i].z);
            Ws[lk16+4*i+3][lrow] = f2tf(wv[i].w);
        }
        __syncthreads();
        #pragma unroll
        for (int kk = 0; kk < 32; kk += 8) {
            unsigned a[2][4], b[4][2];
            #pragma unroll
            for (int mi = 0; mi < 2; mi++) {
                int mb = mw + 16*mi + g;
                a[mi][0] = As[kk+tg  ][mb];
                a[mi][1] = As[kk+tg  ][mb+8];
                a[mi][2] = As[kk+tg+4][mb];
                a[mi][3] = As[kk+tg+4][mb+8];
            }
            #pragma unroll
            for (int j = 0; j < 4; j++) {
                int nb = nw + 8*j + g;
                b[j][0] = Ws[kk+tg  ][nb];
                b[j][1] = Ws[kk+tg+4][nb];
            }
            #pragma unroll
            for (int mi = 0; mi < 2; mi++)
                #pragma unroll
                for (int j = 0; j < 4; j++)
                    mma_tf32(acc[mi][j], a[mi][0], a[mi][1], a[mi][2], a[mi][3], b[j][0], b[j][1]);
        }
        __syncthreads();
    }

    gemm_epilogue(acc, bias1, bias2, res, C, N, act, m0, n0, mw, nw, g, tg);
}

__global__ void __launch_bounds__(128) gemm_kernel(const float* __restrict__ A, const float* __restrict__ W,
                            const float* __restrict__ bias1, const float* __restrict__ bias2,
                            const float* __restrict__ res, float* __restrict__ C,
                            int M, int N, int K, int act)
{
    gemm_tile(A, W, bias1, bias2, res, C, M, N, K, act, blockIdx.y*64, blockIdx.x*64);
}

__global__ void __launch_bounds__(128) qkv_kernel(const float* __restrict__ A,
                           const float* __restrict__ Wq_, const float* __restrict__ Wk_, const float* __restrict__ Wv_,
                           const float* __restrict__ bq_, const float* __restrict__ bk_, const float* __restrict__ bv_,
                           float* __restrict__ Cq, float* __restrict__ Ck, float* __restrict__ Cv)
{
    int z = blockIdx.z;
    const float* W = (z == 0) ? Wq_ : (z == 1) ? Wk_ : Wv_;
    const float* b = (z == 0) ? bq_ : (z == 1) ? bk_ : bv_;
    float*       C = (z == 0) ? Cq  : (z == 1) ? Ck  : Cv;
    gemm_tile(A, W, b, nullptr, nullptr, C, TOK, 256, 256, 0, blockIdx.y*64, blockIdx.x*64);
}

// paired LSTM-input GEMMs (dir 0/1) in one launch via gridDim.z
__global__ void __launch_bounds__(128) lstm_in_kernel(const float* __restrict__ A,
                           const float* __restrict__ W0, const float* __restrict__ W1,
                           const float* __restrict__ b1a, const float* __restrict__ b1b,
                           const float* __restrict__ b2a, const float* __restrict__ b2b,
                           float* __restrict__ C0, float* __restrict__ C1, int K)
{
    int z = blockIdx.z;
    gemm_tile(A, z ? W1 : W0, z ? b2a : b1a, z ? b2b : b1b, nullptr,
              z ? C1 : C0, TOK, 1024, K, 0, blockIdx.y*64, blockIdx.x*64);
}

// ---------------- split-K=2 GEMM for the three proven sites (unchanged) ------
__global__ void __launch_bounds__(256) gemm_sk_kernel(const float* __restrict__ A, const float* __restrict__ W,
                            const float* __restrict__ bias1, const float* __restrict__ bias2,
                            const float* __restrict__ res, float* __restrict__ C,
                            int M, int N, int K, int act)
{
    __shared__ unsigned As[2][16][72];
    __shared__ unsigned Ws[2][16][72];
    __shared__ float red[64][66];
    int m0 = blockIdx.y*64, n0 = blockIdx.x*64;
    int t = threadIdx.x;                 // 256
    int warp = t >> 5, lane = t & 31;
    int kg = warp >> 2;                  // k-group 0/1
    int w4 = warp & 3;
    int mw = (w4 & 1) * 32, nw = (w4 >> 1) * 32;
    int g = lane >> 2, tg = lane & 3;

    float acc[2][4][4];
    #pragma unroll
    for (int mi = 0; mi < 2; mi++)
        #pragma unroll
        for (int j = 0; j < 4; j++)
            #pragma unroll
            for (int e = 0; e < 4; e++) acc[mi][j][e] = 0.f;

    int tt = t & 127;
    int lrow = tt >> 1, lk8 = (tt & 1) * 8;
    int Kh = K >> 1;
    const float* Ap = A + (size_t)(m0 + lrow) * K + (size_t)kg*Kh + lk8;
    const float* Wp = W + (size_t)(n0 + lrow) * K + (size_t)kg*Kh + lk8;

    for (int k0 = 0; k0 < Kh; k0 += 16) {
        float4 av0 = *(const float4*)(Ap + k0);
        float4 av1 = *(const float4*)(Ap + k0 + 4);
        float4 wv0 = *(const float4*)(Wp + k0);
        float4 wv1 = *(const float4*)(Wp + k0 + 4);
        As[kg][lk8+0][lrow] = f2tf(av0.x); As[kg][lk8+1][lrow] = f2tf(av0.y);
        As[kg][lk8+2][lrow] = f2tf(av0.z); As[kg][lk8+3][lrow] = f2tf(av0.w);
        As[kg][lk8+4][lrow] = f2tf(av1.x); As[kg][lk8+5][lrow] = f2tf(av1.y);
        As[kg][lk8+6][lrow] = f2tf(av1.z); As[kg][lk8+7][lrow] = f2tf(av1.w);
        Ws[kg][lk8+0][lrow] = f2tf(wv0.x); Ws[kg][lk8+1][lrow] = f2tf(wv0.y);
        Ws[kg][lk8+2][lrow] = f2tf(wv0.z); Ws[kg][lk8+3][lrow] = f2tf(wv0.w);
        Ws[kg][lk8+4][lrow] = f2tf(wv1.x); Ws[kg][lk8+5][lrow] = f2tf(wv1.y);
        Ws[kg][lk8+6][lrow] = f2tf(wv1.z); Ws[kg][lk8+7][lrow] = f2tf(wv1.w);
        __syncthreads();
        #pragma unroll
        for (int kk = 0; kk < 16; kk += 8) {
            unsigned a[2][4], b[4][2];
            #pragma unroll
            for (int mi = 0; mi < 2; mi++) {
                int mb = mw + 16*mi + g;
                a[mi][0] = As[kg][kk+tg  ][mb];
                a[mi][1] = As[kg][kk+tg  ][mb+8];
                a[mi][2] = As[kg][kk+tg+4][mb];
                a[mi][3] = As[kg][kk+tg+4][mb+8];
            }
            #pragma unroll
            for (int j = 0; j < 4; j++) {
                int nb = nw + 8*j + g;
                b[j][0] = Ws[kg][kk+tg  ][nb];
                b[j][1] = Ws[kg][kk+tg+4][nb];
            }
            #pragma unroll
            for (int mi = 0; mi < 2; mi++)
                #pragma unroll
                for (int j = 0; j < 4; j++)
                    mma_tf32(acc[mi][j], a[mi][0], a[mi][1], a[mi][2], a[mi][3], b[j][0], b[j][1]);
        }
        __syncthreads();
    }

    // reduce group 1 into group 0
    if (kg == 1) {
        #pragma unroll
        for (int mi = 0; mi < 2; mi++)
            #pragma unroll
            for (int j = 0; j < 4; j++)
                #pragma unroll
                for (int half = 0; half < 2; half++) {
                    int row = mw + 16*mi + g + 8*half;
                    int col = nw + 8*j + 2*tg;
                    red[row][col]   = acc[mi][j][2*half+0];
                    red[row][col+1] = acc[mi][j][2*half+1];
                }
    }
    __syncthreads();
    if (kg == 0) {
        #pragma unroll
        for (int mi = 0; mi < 2; mi++)
            #pragma unroll
            for (int j = 0; j < 4; j++)
                #pragma unroll
                for (int half = 0; half < 2; half++) {
                    int row = mw + 16*mi + g + 8*half;
                    int col = nw + 8*j + 2*tg;
                    acc[mi][j][2*half+0] += red[row][col];
                    acc[mi][j][2*half+1] += red[row][col+1];
                }
        gemm_epilogue(acc, bias1, bias2, res, C, N, act, m0, n0, mw, nw, g, tg);
    }
}

// ---------------- layernorm: one warp per row, 8 rows per block --------------
__global__ void __launch_bounds__(256) ln_kernel(const float* __restrict__ x, const float* __restrict__ w,
                          const float* __restrict__ b, float* __restrict__ y,
                          unsigned* __restrict__ stab)
{
    int t = threadIdx.x;
    if (stab && blockIdx.x == 0 && t < 32) stab[t] = 0x007FFFFFu;
    int warp = t >> 5, lane = t & 31;
    int row = blockIdx.x*8 + warp;
    const float* xr = x + (size_t)row*256;
    float v[8];
    float s1 = 0.f, s2 = 0.f;
    #pragma unroll
    for (int j = 0; j < 8; j++) {
        v[j] = xr[lane + 32*j];
        s1 += v[j];
        s2 += v[j]*v[j];
    }
    s1 = wsum(s1);
    s2 = wsum(s2);
    float mu = s1 * (1.0f/256.0f);
    float ri = rsqrtf(s2*(1.0f/256.0f) - mu*mu + 1e-5f);
    float* yr = y + (size_t)row*256;
    #pragma unroll
    for (int j = 0; j < 8; j++) {
        int col = lane + 32*j;
        yr[col] = (v[j] - mu)*ri*w[col] + b[col];
    }
}

// ---------------- FAVOR+ features, merged q/k via blockIdx.z, 4 rows/warp ----
__global__ void __launch_bounds__(128) feat_kernel(const float* __restrict__ qin, const float* __restrict__ kin,
                            const float* __restrict__ proj,
                            float* __restrict__ qp, float* __restrict__ kp,
                            unsigned* __restrict__ stab)
{
    int mode = blockIdx.z;                // 0 = query, 1 = key
    const float* qk = mode ? kin : qin;
    float* out = mode ? kp : qp;
    __shared__ float proj_s[110*33];
    int t = threadIdx.x;   // 128
    for (int i = t; i < 110*33; i += 128) {
        int m = i / 33, d = i - m*33;
        proj_s[i] = (d < 32) ? proj[m*32 + d] : 0.f;
    }
    __syncthreads();
    int warp = t >> 5, lane = t & 31;
    int row0 = blockIdx.x * 32;           // 32 rows per block
    for (int rr = warp*4; rr < 32; rr += 16) {
        float xd[4], dd[4][4];
        #pragma unroll
        for (int q = 0; q < 4; q++) {
            int row = row0 + rr + q;
            int bh = row >> 9, n = row & 511;
            xd[q] = qk[(size_t)((bh >> 3)*512 + n)*256 + (bh & 7)*32 + lane] * SCALE_Q;
            #pragma unroll
            for (int mb = 0; mb < 4; mb++) dd[q][mb] = 0.f;
        }
        #pragma unroll
        for (int d = 0; d < 32; d++) {
            float xv[4];
            #pragma unroll
            for (int q = 0; q < 4; q++) xv[q] = __shfl_sync(0xffffffffu, xd[q], d);
            float p0 = proj_s[lane*33 + d];
            float p1 = proj_s[(lane+32)*33 + d];
            float p2 = proj_s[(lane+64)*33 + d];
            #pragma unroll
            for (int q = 0; q < 4; q++) {
                dd[q][0] += xv[q]*p0;
                dd[q][1] += xv[q]*p1;
                dd[q][2] += xv[q]*p2;
            }
            if (lane < 14) {
                float p3 = proj_s[(lane+96)*33 + d];
                #pragma unroll
                for (int q = 0; q < 4; q++) dd[q][3] += xv[q]*p3;
            }
        }
        #pragma unroll
        for (int q = 0; q < 4; q++) {
            int row = row0 + rr + q;
            int bh = row >> 9;
            float diag = 0.5f * wsum(xd[q]*xd[q]);
            float mx = fmaxf(fmaxf(dd[q][0], dd[q][1]), dd[q][2]);
            if (lane < 14) mx = fmaxf(mx, dd[q][3]);
            mx = wmaxf(mx);
            float* orow = out + (size_t)row*MFEAT;
            if (mode) {
                orow[lane]      = dd[q][0] - diag;
                orow[lane+32]   = dd[q][1] - diag;
                orow[lane+64]   = dd[q][2] - diag;
                if (lane < 14) orow[lane+96] = dd[q][3] - diag;
                if (lane == 0) atomicMax(&stab[bh], fenc(mx));
            } else {
                orow[lane]      = MNS*(expf(dd[q][0] - diag - mx) + EPS_K);
                orow[lane+32]   = MNS*(expf(dd[q][1] - diag - mx) + EPS_K);
                orow[lane+64]   = MNS*(expf(dd[q][2] - diag - mx) + EPS_K);
                if (lane < 14) orow[lane+96] = MNS*(expf(dd[q][3] - diag - mx) + EPS_K);
            }
        }
    }
}

// ---------------- attention pass 1: normalize kp + per-chunk totals ----------
__global__ void attn_sum_kernel(float* __restrict__ kp, const float* __restrict__ v,
                                const unsigned* __restrict__ stab, float* __restrict__ T)
{
    __shared__ float kp_c[CHUNK*MFEAT];
    __shared__ float v_c [CHUNK*32];
    int ch = blockIdx.x, bh = blockIdx.y;
    int b = bh >> 3, h = bh & 7;
    int t = threadIdx.x;                 // 256
    float stv = fdec(stab[bh]);
    float* kpb = kp + (size_t)bh*NSEQ*MFEAT + (size_t)ch*CHUNK*MFEAT;
    for (int i = t; i < CHUNK*MFEAT; i += 256) {
        float e = MNS*(expf(kpb[i] - stv) + EPS_K);
        kp_c[i] = e;
        kpb[i] = e;                      // normalized for attn_scan
    }
    for (int i = t; i < CHUNK*32; i += 256) {
        int n = i >> 5, d = i & 31;
        v_c[i] = v[(size_t)(b*512 + ch*CHUNK + n)*256 + h*32 + d];
    }
    __syncthreads();

    int mg = t >> 5, d = t & 31;
    float S[14];
    #pragma unroll
    for (int j = 0; j < 14; j++) S[j] = 0.f;
    for (int n = 0; n < CHUNK; n++) {
        float vd = v_c[n*32 + d];
        #pragma unroll
        for (int j = 0; j < 14; j++) {
            int m = mg + 8*j;
            if (m < MFEAT) S[j] += kp_c[n*MFEAT + m]*vd;
        }
    }
    float* Tb = T + (size_t)(bh*NCHUNK + ch)*STATE;
    #pragma unroll
    for (int j = 0; j < 14; j++) {
        int m = mg + 8*j;
        if (m < MFEAT) Tb[m*33 + d] = S[j];
    }
    if (t < MFEAT) {
        float z = 0.f;
        for (int n = 0; n < CHUNK; n++) z += kp_c[n*MFEAT + t];
        Tb[t*33 + 32] = z;
    }
}

// ---------------- attention pass 2: within-chunk scan, double-buffered -------
__global__ void attn_scan_kernel(const float* __restrict__ qp, const float* __restrict__ kp,
                                 const float* __restrict__ v, const float* __restrict__ T,
                                 float* __restrict__ o)
{
    __shared__ float kp_c[CHUNK*MFEAT];
    __shared__ float qp_c[CHUNK*MFEAT];
    __shared__ float v_c [CHUNK*32];
    __shared__ float qz_s[2][MFEAT];
    __shared__ float part_s[2][8][33];
    int ch = blockIdx.x, bh = blockIdx.y;
    int b = bh >> 3, h = bh & 7;
    int t = threadIdx.x;                 // 256
    const float* kpb = kp + (size_t)bh*NSEQ*MFEAT + (size_t)ch*CHUNK*MFEAT;
    const float* qpb = qp + (size_t)bh*NSEQ*MFEAT + (size_t)ch*CHUNK*MFEAT;
    for (int i = t; i < CHUNK*MFEAT; i += 256) { kp_c[i] = kpb[i]; qp_c[i] = qpb[i]; }
    for (int i = t; i < CHUNK*32; i += 256) {
        int n = i >> 5, d = i & 31;
        v_c[i] = v[(size_t)(b*512 + ch*CHUNK + n)*256 + h*32 + d];
    }
    int mg = t >> 5, d = t & 31;
    // inline exclusive prefix over earlier chunks (same summation order)
    float S[14];
    #pragma unroll
    for (int j = 0; j < 14; j++) S[j] = 0.f;
    float z = 0.f;
    for (int c = 0; c < ch; c++) {
        const float* Tc = T + (size_t)(bh*NCHUNK + c)*STATE;
        #pragma unroll
        for (int j = 0; j < 14; j++) {
            int m = mg + 8*j;
            if (m < MFEAT) S[j] += Tc[m*33 + d];
        }
        if (t < MFEAT) z += Tc[t*33 + 32];
    }
    __syncthreads();

    for (int n = 0; n < CHUNK; n++) {
        int pb = n & 1;
        if (t < MFEAT) { z += kp_c[n*MFEAT + t]; qz_s[pb][t] = qp_c[n*MFEAT + t]*z; }
        float vd = v_c[n*32 + d];
        float acc = 0.f;
        #pragma unroll
        for (int j = 0; j < 14; j++) {
            int m = mg + 8*j;
            if (m < MFEAT) {
                S[j] += kp_c[n*MFEAT + m]*vd;
                acc  += qp_c[n*MFEAT + m]*S[j];
            }
        }
        part_s[pb][mg][d] = acc;
        __syncthreads();
        if (t < 32) {
            float qs = qz_s[pb][t] + qz_s[pb][t+32] + qz_s[pb][t+64] + ((t < 14) ? qz_s[pb][t+96] : 0.f);
            float denom = wsum(qs) + EPS_D;
            float s = 0.f;
            #pragma unroll
            for (int g = 0; g < 8; g++) s += part_s[pb][g][t];
            o[(size_t)(b*512 + ch*CHUNK + n)*256 + h*32 + t] = s / denom;
        }
        // no trailing sync: next iter writes the other buffer
    }
}

// ---------------- BiLSTM scan: 8-CTA cluster, st.async mbarrier handshake ----
__global__ void __cluster_dims__(8,1,1) __launch_bounds__(256,1)
lstm_kernel(const float* __restrict__ gi,      // [2][2048][1024] dir-major
            const float* __restrict__ whh,     // [2][1024][256]  dir-major
            float* __restrict__ out)           // [2048][512]
{
    __shared__ __align__(16) float h_buf[512];
    __shared__ float part_s[256];
    __shared__ float gates_s[128];
    __shared__ __align__(16) unsigned long long mbar[2];

    int t   = threadIdx.x;              // 256
    int cta = blockIdx.x;
    int r   = cta & 7;
    int s   = cta >> 3;
    int b   = s >> 1, dir = s & 1;

    const float* whh_d = whh + (size_t)dir*1024*256;
    const float* gi_d  = gi  + (size_t)dir*TOK*1024 + (size_t)b*512*1024;

    int half = t >> 7, row = t & 127;
    int gate = row >> 5, jl = row & 31;
    const float* wp = whh_d + (size_t)(gate*256 + 32*r + jl)*256 + 128*half;

    unsigned long long w2[64];
    #pragma unroll
    for (int c = 0; c < 32; c++) {
        ulonglong2 u = *(const ulonglong2*)(wp + 4*c);
        w2[2*c]   = u.x;
        w2[2*c+1] = u.y;
    }

    h_buf[t] = 0.f;
    h_buf[256 + t] = 0.f;
    uint32_t hb = (uint32_t)__cvta_generic_to_shared(h_buf);
    uint32_t mb = (uint32_t)__cvta_generic_to_shared(mbar);
    if (t == 0) {
        asm volatile("mbarrier.init.shared.b64 [%0], 1;" :: "r"(mb)     : "memory");
        asm volatile("mbarrier.init.shared.b64 [%0], 1;" :: "r"(mb + 8) : "memory");
    }
    float c_reg = 0.f;
    int gidx = ((t >> 5) << 8) + 32*r + (t & 31);   // valid for t<128
    __syncthreads();
    asm volatile("barrier.cluster.arrive.aligned;\n\tbarrier.cluster.wait.aligned;" ::: "memory");

    uint32_t peer_base[8];
    if (t < 32) {
        #pragma unroll
        for (int p = 0; p < 8; p++) {
            uint32_t pb;
            asm volatile("mapa.shared::cluster.u32 %0, %1, %2;" : "=r"(pb) : "r"(hb), "r"(p));
            peer_base[p] = pb;
        }
    }
    uint32_t mb_off = mb - hb;

    float pg = 0.f;
    if (t < 128) pg = gi_d[(size_t)(dir ? 511 : 0)*1024 + gidx];

    int par0 = 0, par1 = 0;
    for (int step = 0; step < 512; step++) {
        int mi = step & 1;
        if (step > 0) {
            uint32_t ma = mb + mi*8;
            int ph = mi ? par1 : par0;
            unsigned done;
            asm volatile(
                "{\n\t.reg .pred p;\n\t"
                "mbarrier.try_wait.parity.acquire.cta.shared::cta.b64 p, [%1], %2;\n\t"
                "selp.b32 %0, 1, 0, p;\n\t}"
                : "=r"(done) : "r"(ma), "r"(ph) : "memory");
            if (!done) {
                asm volatile(
                    "{\n\t.reg .pred P1;\n\t"
                    "WL_%=:\n\t"
                    "mbarrier.try_wait.parity.acquire.cta.shared::cta.b64 P1, [%0], %1, 0x989680;\n\t"
                    "@P1 bra.uni WD_%=;\n\t"
                    "bra.uni WL_%=;\n\t"
                    "WD_%=:\n\t}"
                    :: "r"(ma), "r"(ph) : "memory");
            }
            if (mi) par1 ^= 1; else par0 ^= 1;
        }
        if (t == 0 && step + 1 < 512) {
            uint32_t ma = mb + (mi ^ 1)*8;
            asm volatile("mbarrier.arrive.expect_tx.shared.b64 _, [%0], %1;"
                         :: "r"(ma), "r"(1024) : "memory");
        }
        int n = dir ? (511 - step) : step;
        const float* hr = h_buf + mi*256 + 128*half;
        unsigned long long a0 = 0ull, a1 = 0ull, a2 = 0ull, a3 = 0ull;
        #pragma unroll
        for (int c = 0; c < 16; c++) {
            ulonglong2 h0 = *(const ulonglong2*)(hr + 8*c);
            ulonglong2 h1 = *(const ulonglong2*)(hr + 8*c + 4);
            ffma2(a0, w2[4*c+0], h0.x);
            ffma2(a1, w2[4*c+1], h0.y);
            ffma2(a2, w2[4*c+2], h1.x);
            ffma2(a3, w2[4*c+3], h1.y);
        }
        part_s[half*128 + row] = (f2lo(a0) + f2hi(a0)) + (f2lo(a1) + f2hi(a1))
                               + (f2lo(a2) + f2hi(a2)) + (f2lo(a3) + f2hi(a3));
        __syncthreads();
        if (t < 128) {
            gates_s[t] = pg + part_s[t] + part_s[128 + t];
            if (step + 1 < 512)
                pg = gi_d[(size_t)(dir ? (510 - step) : (step + 1))*1024 + gidx];
        }
        __syncthreads();
        if (t < 32) {
            float ig = gates_s[t], fg = gates_s[32+t], gg = gates_s[64+t], og = gates_s[96+t];
            c_reg = sigm(fg)*c_reg + sigm(ig)*tanhf(gg);
            float hval = sigm(og)*tanhf(c_reg);
            out[(size_t)(b*512 + n)*512 + dir*256 + 32*r + t] = hval;
            if (step + 1 < 512) {
                uint32_t off_h = (uint32_t)((((mi ^ 1)*256) + 32*r + t) << 2);
                uint32_t rm_off = mb_off + (uint32_t)((mi ^ 1)*8);
                unsigned hv = __float_as_uint(hval);
                #pragma unroll
                for (int p = 0; p < 8; p++) {
                    uint32_t ra = peer_base[p] + off_h;
                    uint32_t rm = peer_base[p] + rm_off;
                    asm volatile("st.async.shared::cluster.mbarrier::complete_tx::bytes.b32 [%0], %1, [%2];"
                                 :: "r"(ra), "r"(hv), "r"(rm) : "memory");
                }
            }
        }
    }
}

// ---------------- final head ----------------
__global__ void fc_kernel(const float* __restrict__ hin, const float* __restrict__ fw,
                          const float* __restrict__ fb, float* __restrict__ outp)
{
    int t = threadIdx.x;           // 128
    int warp = t >> 5, lane = t & 31;
    const float* rowp = hin + (size_t)(warp*512 + 511)*512;
    float s = 0.f;
    for (int j = lane; j < 512; j += 32) s += rowp[j]*fw[j];
    s = wsum(s);
    if (lane == 0) outp[warp] = s + fb[0];
}

// ---------------- launch ----------------
static float* sym_f(const void* s) { void* p = nullptr; cudaGetSymbolAddress(&p, s); return (float*)p; }

extern "C" void kernel_launch(void* const* d_in, const int* in_sizes, int n_in,
                              void* d_out, int out_size)
{
    (void)in_sizes; (void)n_in; (void)out_size;
    const float* x      = (const float*)d_in[0];
    const float* Win_w  = (const float*)d_in[1];
    const float* Win_b  = (const float*)d_in[2];
    const float* ln1_w  = (const float*)d_in[3];
    const float* ln1_b  = (const float*)d_in[4];
    const float* Wq     = (const float*)d_in[5];
    const float* bq     = (const float*)d_in[6];
    const float* Wk     = (const float*)d_in[7];
    const float* bk     = (const float*)d_in[8];
    const float* Wv     = (const float*)d_in[9];
    const float* bv     = (const float*)d_in[10];
    const float* Wo     = (const float*)d_in[11];
    const float* bo     = (const float*)d_in[12];
    const float* proj   = (const float*)d_in[13];
    const float* ln2_w  = (const float*)d_in[14];
    const float* ln2_b  = (const float*)d_in[15];
    const float* Wff1   = (const float*)d_in[16];
    const float* bff1   = (const float*)d_in[17];
    const float* Wff2   = (const float*)d_in[18];
    const float* bff2   = (const float*)d_in[19];
    const float* Wih0   = (const float*)d_in[20];
    const float* Whh0   = (const float*)d_in[21];
    const float* b0     = (const float*)d_in[22];
    const float* Wih12  = (const float*)d_in[23];
    const float* Whh12  = (const float*)d_in[24];
    const float* b12    = (const float*)d_in[25];
    const float* fc_w   = (const float*)d_in[26];
    const float* fc_b   = (const float*)d_in[27];

    float* ph  = sym_f(g_h);
    float* py  = sym_f(g_y);
    float* pq  = sym_f(g_q);
    float* pk  = sym_f(g_k);
    float* pv  = sym_f(g_v);
    float* po  = sym_f(g_o);
    float* pff = sym_f(g_ff);
    float* pqp = sym_f(g_qp);
    float* pkp = sym_f(g_kp);
    float* pT  = sym_f(g_T);
    float* pgi = sym_f(g_gi);
    float* pl0 = sym_f(g_l0);
    float* pl1 = sym_f(g_l1);
    unsigned* pstab = nullptr;
    { void* p = nullptr; cudaGetSymbolAddress(&p, g_stab); pstab = (unsigned*)p; }

    dim3 g256(256/64, TOK/64), g1024(1024/64, TOK/64);
    dim3 gqkv(256/64, TOK/64, 3);
    dim3 glstm(1024/64, TOK/64, 2);
    dim3 gfeat(512, 1, 2);
    dim3 gattn(NCHUNK, 32);

    // input projection (split-K)
    gemm_sk_kernel<<<g256, 256>>>(x, Win_w, Win_b, nullptr, nullptr, ph, TOK, 256, 128, 0);

    for (int l = 0; l < NLAYERS; l++) {
        const float* prj = proj + (size_t)l*MFEAT*DH;
        ln_kernel<<<TOK/8, 256>>>(ph, ln1_w + l*256, ln1_b + l*256, py, pstab);
        qkv_kernel<<<gqkv, 128>>>(py, Wq + (size_t)l*256*256, Wk + (size_t)l*256*256, Wv + (size_t)l*256*256,
                                  bq + l*256, bk + l*256, bv + l*256, pq, pk, pv);
        feat_kernel<<<gfeat, 128>>>(pq, pk, prj, pqp, pkp, pstab);
        attn_sum_kernel<<<gattn, 256>>>(pkp, pv, pstab, pT);
        attn_scan_kernel<<<gattn, 256>>>(pqp, pkp, pv, pT, po);
        gemm_sk_kernel<<<g256, 256>>>(po, Wo + (size_t)l*256*256, bo + l*256, nullptr, ph, ph, TOK, 256, 256, 0);
        ln_kernel<<<TOK/8, 256>>>(ph, ln2_w + l*256, ln2_b + l*256, py, nullptr);
        gemm_kernel<<<g1024, 128>>>(py, Wff1 + (size_t)l*1024*256, bff1 + l*1024, nullptr, nullptr, pff, TOK, 1024, 256, 1);
        gemm_sk_kernel<<<g256, 256>>>(pff, Wff2 + (size_t)l*256*1024, bff2 + l*256, nullptr, ph, ph, TOK, 256, 1024, 0);
    }

    // ---- BiLSTM layer 0 (input D=256): both dirs in one launch ----
    lstm_in_kernel<<<glstm, 128>>>(ph, Wih0, Wih0 + 1024*256,
                                   b0, b0 + 1024, b0 + 2048, b0 + 3072,
                                   pgi, pgi + TOK*1024, 256);
    lstm_kernel<<<64, 256>>>(pgi, Whh0, pl0);

    // ---- BiLSTM layers 1,2 (input 2*HID=512) ----
    float* lin = pl0;
    float* lo  = pl1;
    for (int ll = 0; ll < 2; ll++) {
        const float* w0  = Wih12 + (size_t)(ll*2 + 0)*1024*512;
        const float* w1  = Wih12 + (size_t)(ll*2 + 1)*1024*512;
        const float* b1a = b12 + (size_t)((ll*2 + 0)*2 + 0)*1024;
        const float* b1b = b12 + (size_t)((ll*2 + 0)*2 + 1)*1024;
        const float* b2a = b12 + (size_t)((ll*2 + 1)*2 + 0)*1024;
        const float* b2b = b12 + (size_t)((ll*2 + 1)*2 + 1)*1024;
        lstm_in_kernel<<<glstm, 128>>>(lin, w0, w1, b1a, b1b, b2a, b2b,
                                       pgi, pgi + TOK*1024, 512);
        lstm_kernel<<<64, 256>>>(pgi, Whh12 + (size_t)ll*2*1024*256, lo);
        float* tmp = lin; lin = lo; lo = tmp;
    }

    // ---- final head ----
    fc_kernel<<<1, 128>>>(lin, fc_w, fc_b, (float*)d_out);
}